// round 8
// baseline (speedup 1.0000x reference)
#include <cuda_runtime.h>
#include <math.h>
#include <stdint.h>

#define Cn 512
#define Bn 64
#define Nn 1024
#define Mn 16
#define SCALE 0.04419417382415922f   // 512^-0.5

// ---------------- scratch (allocation-free) ----------------
__device__ float g_xp  [1024 * 512];
__device__ float g_A   [1024 * 512];
__device__ float g_Aq  [1024 * 512];
__device__ float g_Ak  [1024 * 512];
__device__ float g_bqA [1024];
__device__ float g_v   [512];           // Wq^T bq (coldot)
__device__ float g_bvo [512];           // Wo @ bv (rowdot)
__device__ float g_WqT [512 * 512];
__device__ float g_WvT [512 * 512];
__device__ float g_WoT [512 * 512];
__device__ float g_WcT [512 * 512];     // WvT @ WoT
__device__ float g_L2  [64 * 16 * 1024];
__device__ float g_L1  [64 * 1024 * 16];
__device__ float g_xa  [1024 * 512];
__device__ float g_AFo [1024 * 512];

__device__ __forceinline__ uint32_t smem_u32(const void* p) {
    return (uint32_t)__cvta_generic_to_shared(p);
}
__device__ __forceinline__ void cp_async16(uint32_t s, const void* g) {
    asm volatile("cp.async.cg.shared.global [%0], [%1], 16;" :: "r"(s), "l"(g));
}

// ================= prep: 3 transposes + v + bvo, one launch =================
// grid (16,16,4), block (32,8). z<3: transpose; z==3: vector work.
__global__ void prep_kernel(const float* __restrict__ Wq, const float* __restrict__ Wv,
                            const float* __restrict__ Wo, const float* __restrict__ bq,
                            const float* __restrict__ bv,
                            float* __restrict__ WqT, float* __restrict__ WvT,
                            float* __restrict__ WoT, float* __restrict__ v,
                            float* __restrict__ bvo)
{
    if (blockIdx.z < 3) {
        __shared__ float t[32][33];
        const float* s; float* d;
        if (blockIdx.z == 0)      { s = Wq; d = WqT; }
        else if (blockIdx.z == 1) { s = Wv; d = WvT; }
        else                      { s = Wo; d = WoT; }
        const int x  = blockIdx.x * 32 + threadIdx.x;
        const int y0 = blockIdx.y * 32 + threadIdx.y;
#pragma unroll
        for (int j = 0; j < 32; j += 8)
            t[threadIdx.y + j][threadIdx.x] = s[(size_t)(y0 + j) * Cn + x];
        __syncthreads();
        const int ox  = blockIdx.y * 32 + threadIdx.x;
        const int oy0 = blockIdx.x * 32 + threadIdx.y;
#pragma unroll
        for (int j = 0; j < 32; j += 8)
            d[(size_t)(oy0 + j) * Cn + ox] = t[threadIdx.x][threadIdx.y + j];
        return;
    }
    // vector work
    const int id  = blockIdx.y * 16 + blockIdx.x;
    const int tid = threadIdx.y * 32 + threadIdx.x;
    if (id < 2) {
        // v[n] = sum_c Wq[c,n] * bq[c]  (coldot, coalesced over n)
        const int n = id * 256 + tid;
        float s = 0.f;
#pragma unroll 8
        for (int c = 0; c < Cn; c++) s = fmaf(__ldg(&Wq[(size_t)c * Cn + n]), __ldg(&bq[c]), s);
        v[n] = s;
    } else if (id < 66) {
        // bvo[r] = Wo[r,:] . bv  (warp per row)
        const int row  = (id - 2) * 8 + (tid >> 5);
        const int lane = tid & 31;
        const float* sr = Wo + (size_t)row * Cn;
        float s = 0.f;
#pragma unroll
        for (int k = 0; k < 16; k++) s += sr[lane + 32 * k] * __ldg(&bv[lane + 32 * k]);
#pragma unroll
        for (int off = 16; off > 0; off >>= 1) s += __shfl_xor_sync(0xffffffffu, s, off);
        if (lane == 0) bvo[row] = s;
    }
}

// ================= pool + bqA: xp[bm,:] and bqA[bm] = xp[bm]. v =================
__global__ __launch_bounds__(512)
void pool_bqa_kernel(const float* __restrict__ x, const float* __restrict__ v,
                     float* __restrict__ xp, float* __restrict__ bqA)
{
    __shared__ float red[512];
    const int bm = blockIdx.x;
    const int c  = threadIdx.x;
    const float* base = x + (size_t)bm * 64 * Cn + c;
    float s = 0.f;
#pragma unroll 8
    for (int t = 0; t < 64; t++) s += base[(size_t)t * Cn];
    const float xv = s * (1.0f / 64.0f);
    xp[(size_t)bm * Cn + c] = xv;

    red[c] = xv * __ldg(&v[c]);
    __syncthreads();
    for (int st = 256; st > 32; st >>= 1) {
        if (c < st) red[c] += red[c + st];
        __syncthreads();
    }
    if (c < 32) {
        float r = red[c] + red[c + 32];
#pragma unroll
        for (int off = 16; off > 0; off >>= 1) r += __shfl_xor_sync(0xffffffffu, r, off);
        if (c == 0) bqA[bm] = r;
    }
}

// ================= NN GEMM, two independent problems in one launch =================
// 1-D grid; blocks [0,nblk0) -> problem 0, rest -> problem 1.
// Each problem: N=512 (8 n-blocks), rows = (#blocks/8)*64, K=512.
#define XS_FLOATS (64 * 36)
#define WS_FLOATS (32 * 68)
#define STAGE_FLOATS (XS_FLOATS + WS_FLOATS)
#define GEMM_SMEM (3 * STAGE_FLOATS * 4)

__global__ __launch_bounds__(256)
void gemm_nn(const float* __restrict__ X0, const float* __restrict__ W0,
             const float* __restrict__ b0, float* __restrict__ Y0,
             const float* __restrict__ X1, const float* __restrict__ W1,
             const float* __restrict__ b1, float* __restrict__ Y1, int nblk0)
{
    extern __shared__ float sm[];
    const int tid = threadIdx.x;
    const int tx = tid & 15, ty = tid >> 4;
    const float *X, *W, *bias; float* Y; int local;
    if ((int)blockIdx.x < nblk0) { X = X0; W = W0; bias = b0; Y = Y0; local = blockIdx.x; }
    else                         { X = X1; W = W1; bias = b1; Y = Y1; local = blockIdx.x - nblk0; }
    const int n0 = (local & 7) * 64;
    const int r0 = (local >> 3) * 64;

    const int xlr = tid >> 2, xlk = (tid & 3) * 8;
    const int wwk = tid >> 3, wwn = (tid & 7) * 8;
    const float* gX = X + (size_t)(r0 + xlr) * Cn + xlk;
    const float* gW = W + (size_t)wwk * Cn + n0 + wwn;
    const uint32_t sbase = smem_u32(sm);
    const uint32_t xdst = sbase + (uint32_t)(xlr * 36 + xlk) * 4u;
    const uint32_t wdst = sbase + (uint32_t)(XS_FLOATS + wwk * 68 + wwn) * 4u;

#define G_LOAD(ST, K0)                                                          \
    do {                                                                        \
        const uint32_t so_ = (uint32_t)(ST) * (STAGE_FLOATS * 4u);              \
        cp_async16(xdst + so_,      gX + (K0));                                 \
        cp_async16(xdst + so_ + 16, gX + (K0) + 4);                             \
        cp_async16(wdst + so_,      gW + (size_t)(K0) * Cn);                    \
        cp_async16(wdst + so_ + 16, gW + (size_t)(K0) * Cn + 4);                \
        asm volatile("cp.async.commit_group;" ::: "memory");                    \
    } while (0)

    float acc[4][4];
#pragma unroll
    for (int i = 0; i < 4; i++)
#pragma unroll
        for (int j = 0; j < 4; j++) acc[i][j] = 0.f;

    G_LOAD(0, 0);
    G_LOAD(1, 32);

#pragma unroll 1
    for (int it = 0; it < 16; it++) {
        if (it < 15) asm volatile("cp.async.wait_group 1;" ::: "memory");
        else         asm volatile("cp.async.wait_group 0;" ::: "memory");
        __syncthreads();
        if (it + 2 < 16) G_LOAD((it + 2) % 3, (it + 2) * 32);

        const float* Xst = sm + (it % 3) * STAGE_FLOATS;
        const float* Wst = Xst + XS_FLOATS;
#pragma unroll
        for (int k4 = 0; k4 < 8; k4++) {
            float aa[4][4], bb[4][4];
#pragma unroll
            for (int i = 0; i < 4; i++) {
                float4 a = *(const float4*)(Xst + (ty * 4 + i) * 36 + k4 * 4);
                aa[i][0] = a.x; aa[i][1] = a.y; aa[i][2] = a.z; aa[i][3] = a.w;
            }
#pragma unroll
            for (int q = 0; q < 4; q++) {
                float4 b = *(const float4*)(Wst + (k4 * 4 + q) * 68 + tx * 4);
                bb[q][0] = b.x; bb[q][1] = b.y; bb[q][2] = b.z; bb[q][3] = b.w;
            }
#pragma unroll
            for (int i = 0; i < 4; i++)
#pragma unroll
                for (int j = 0; j < 4; j++)
#pragma unroll
                    for (int q = 0; q < 4; q++)
                        acc[i][j] = fmaf(aa[i][q], bb[q][j], acc[i][j]);
        }
    }
#undef G_LOAD

    float4 bi = make_float4(0.f, 0.f, 0.f, 0.f);
    if (bias) bi = *(const float4*)(bias + n0 + tx * 4);
#pragma unroll
    for (int i = 0; i < 4; i++) {
        float4 o;
        o.x = acc[i][0] + bi.x; o.y = acc[i][1] + bi.y;
        o.z = acc[i][2] + bi.z; o.w = acc[i][3] + bi.w;
        *(float4*)(Y + (size_t)(r0 + ty * 4 + i) * Cn + n0 + tx * 4) = o;
    }
}

// ================= fused logits: L1[b,n,m], L2[b,m,n] =================
#define L12_SMEM (2 * 16 * 512 * 4 + 64 * 128 * 4 + 64)
__global__ __launch_bounds__(256)
void logits12_kernel(const float* __restrict__ Aq, const float* __restrict__ Ak,
                     const float* __restrict__ bqA, const float* __restrict__ x,
                     float* __restrict__ L1, float* __restrict__ L2)
{
    extern __shared__ float sm[];
    float* Aq_s = sm;
    float* Ak_s = sm + 8192;
    float* xs   = sm + 16384;
    float* bq_s = sm + 24576;
    const int b   = blockIdx.y;
    const int n0  = blockIdx.x * 128;
    const int tid = threadIdx.x;
    const int mi  = tid >> 6;
    const int ni  = tid & 63;
    const int lnr = tid >> 1;
    const int le  = tid & 1;

    {
        const float4* sq = (const float4*)(Aq + (size_t)b * 16 * Cn);
        const float4* sk = (const float4*)(Ak + (size_t)b * 16 * Cn);
        float4* dq = (float4*)Aq_s;
        float4* dk = (float4*)Ak_s;
        for (int i = tid; i < 2048; i += 256) { dq[i] = sq[i]; dk[i] = sk[i]; }
        if (tid < 16) bq_s[tid] = bqA[b * 16 + tid];
    }

    float acc1[4][2] = {}, acc2[4][2] = {};
    for (int kt = 0; kt < 8; kt++) {
        __syncthreads();
        const float* gx = x + ((size_t)b * Nn + n0 + lnr) * Cn + kt * 64 + le * 32;
#pragma unroll
        for (int f = 0; f < 8; f++) {
            float4 vv = *(const float4*)(gx + f * 4);
            const int k = le * 32 + f * 4;
            xs[(k + 0) * 128 + lnr] = vv.x;
            xs[(k + 1) * 128 + lnr] = vv.y;
            xs[(k + 2) * 128 + lnr] = vv.z;
            xs[(k + 3) * 128 + lnr] = vv.w;
        }
        __syncthreads();
        const float* aqb = Aq_s + (size_t)mi * 4 * Cn + kt * 64;
        const float* akb = Ak_s + (size_t)mi * 4 * Cn + kt * 64;
#pragma unroll 8
        for (int k = 0; k < 64; k++) {
            float2 xv = *(const float2*)(xs + k * 128 + 2 * ni);
#pragma unroll
            for (int j = 0; j < 4; j++) {
                float aq = aqb[j * Cn + k];
                float ak = akb[j * Cn + k];
                acc1[j][0] = fmaf(aq, xv.x, acc1[j][0]);
                acc1[j][1] = fmaf(aq, xv.y, acc1[j][1]);
                acc2[j][0] = fmaf(ak, xv.x, acc2[j][0]);
                acc2[j][1] = fmaf(ak, xv.y, acc2[j][1]);
            }
        }
    }
#pragma unroll
    for (int j = 0; j < 4; j++) {
        float2 o = make_float2(acc2[j][0] * SCALE, acc2[j][1] * SCALE);
        *(float2*)(L2 + ((size_t)b * 16 + mi * 4 + j) * Nn + n0 + 2 * ni) = o;
    }
    {
        float4 o0, o1;
        float* p0 = (float*)&o0; float* p1 = (float*)&o1;
#pragma unroll
        for (int j = 0; j < 4; j++) {
            p0[j] = (acc1[j][0] + bq_s[mi * 4 + j]) * SCALE;
            p1[j] = (acc1[j][1] + bq_s[mi * 4 + j]) * SCALE;
        }
        *(float4*)(L1 + ((size_t)b * Nn + n0 + 2 * ni)     * 16 + mi * 4) = o0;
        *(float4*)(L1 + ((size_t)b * Nn + n0 + 2 * ni + 1) * 16 + mi * 4) = o1;
    }
}

// ================= in-place softmax over rows of 1024 =================
__global__ __launch_bounds__(256)
void softmax_rows(float* __restrict__ L)
{
    __shared__ float red[256];
    float* row = L + (size_t)blockIdx.x * Nn;
    const int tid = threadIdx.x;
    float vv[4];
    float mx = -INFINITY;
#pragma unroll
    for (int i = 0; i < 4; i++) { vv[i] = row[tid + i * 256]; mx = fmaxf(mx, vv[i]); }
    red[tid] = mx; __syncthreads();
    for (int s = 128; s > 0; s >>= 1) {
        if (tid < s) red[tid] = fmaxf(red[tid], red[tid + s]);
        __syncthreads();
    }
    mx = red[0]; __syncthreads();
    float sum = 0.f;
#pragma unroll
    for (int i = 0; i < 4; i++) { vv[i] = __expf(vv[i] - mx); sum += vv[i]; }
    red[tid] = sum; __syncthreads();
    for (int s = 128; s > 0; s >>= 1) {
        if (tid < s) red[tid] += red[tid + s];
        __syncthreads();
    }
    const float inv = 1.0f / red[0];
#pragma unroll
    for (int i = 0; i < 4; i++) row[tid + i * 256] = vv[i] * inv;
}

// ================= xa[b,m,:] = P2[b,m,:] @ x[b] (P2 tiles staged) =================
__global__ __launch_bounds__(256)
void xa_kernel(const float* __restrict__ P, const float* __restrict__ x,
               float* __restrict__ xa)
{
    __shared__ float xs[64][132];     // 33 KB
    __shared__ float ps[16][64];      // 4 KB
    const int b   = blockIdx.y;
    const int c0  = blockIdx.x * 128;
    const int tid = threadIdx.x;
    const int mi  = tid >> 6;
    const int ci  = tid & 63;
    const int lnr = tid >> 3;
    float acc[4][2] = {};

    for (int nt = 0; nt < 16; nt++) {
        __syncthreads();
#pragma unroll
        for (int h = 0; h < 2; h++) {
            const int n = lnr + h * 32;
            const float* gx = x + ((size_t)b * Nn + nt * 64 + n) * Cn + c0;
#pragma unroll
            for (int q = 0; q < 4; q++) {
                const int cc = ((tid & 7) + q * 8) * 4;
                *(float4*)(&xs[n][cc]) = *(const float4*)(gx + cc);
            }
        }
        {
            const int i = tid * 4;       // 1024 floats = 16x64
            if (i < 1024) {
                const int m = i >> 6, n = i & 63;
                *(float4*)(&ps[m][n]) =
                    *(const float4*)(P + ((size_t)b * 16 + m) * Nn + nt * 64 + n);
            }
        }
        __syncthreads();
#pragma unroll 8
        for (int n = 0; n < 64; n++) {
            float2 xv = *(const float2*)(&xs[n][2 * ci]);
#pragma unroll
            for (int j = 0; j < 4; j++) {
                float p = ps[mi * 4 + j][n];
                acc[j][0] = fmaf(p, xv.x, acc[j][0]);
                acc[j][1] = fmaf(p, xv.y, acc[j][1]);
            }
        }
    }
#pragma unroll
    for (int j = 0; j < 4; j++)
        *(float2*)(xa + ((size_t)b * 16 + mi * 4 + j) * Cn + c0 + 2 * ci)
            = make_float2(acc[j][0], acc[j][1]);
}

// ================= final (float4 inner) =================
__global__ __launch_bounds__(512)
void final_kernel(const float* __restrict__ L1, const float* __restrict__ AFo,
                  const float* __restrict__ bo, float* __restrict__ out)
{
    __shared__ float4 afo4[Mn * 128];    // 32 KB
    __shared__ float  l1s[64 * 16];      // 4 KB
    __shared__ float4 bo4[128];          // 2 KB
    const int b    = blockIdx.y;
    const int n0   = blockIdx.x * 64;
    const int tid  = threadIdx.x;
    const int warp = tid >> 5;
    const int lane = tid & 31;

    {
        const float4* s = (const float4*)(AFo + (size_t)b * Mn * Cn);
        for (int i = tid; i < 2048; i += 512) afo4[i] = s[i];
        const float4* sl = (const float4*)(L1 + ((size_t)b * Nn + n0) * 16);
        if (tid < 256) ((float4*)l1s)[tid] = sl[tid];
        if (tid < 128) bo4[tid] = ((const float4*)bo)[tid];
    }
    __syncthreads();

#pragma unroll
    for (int t = 0; t < 4; t++) {
        const int tok = warp * 4 + t;
        float lg[16];
#pragma unroll
        for (int m = 0; m < Mn; m++) lg[m] = l1s[tok * 16 + m];
        float mx = lg[0];
#pragma unroll
        for (int m = 1; m < Mn; m++) mx = fmaxf(mx, lg[m]);
        float s = 0.f;
#pragma unroll
        for (int m = 0; m < Mn; m++) { lg[m] = __expf(lg[m] - mx); s += lg[m]; }
        const float inv = 1.0f / s;

        float4* orow = (float4*)(out + ((size_t)b * Nn + n0 + tok) * Cn);
#pragma unroll
        for (int kc = 0; kc < 4; kc++) {
            const int cidx = kc * 32 + lane;
            float4 acc = make_float4(0.f, 0.f, 0.f, 0.f);
#pragma unroll
            for (int m = 0; m < Mn; m++) {
                float4 f = afo4[m * 128 + cidx];
                acc.x = fmaf(lg[m], f.x, acc.x);
                acc.y = fmaf(lg[m], f.y, acc.y);
                acc.z = fmaf(lg[m], f.z, acc.z);
                acc.w = fmaf(lg[m], f.w, acc.w);
            }
            float4 bb = bo4[cidx];
            acc.x = acc.x * inv + bb.x;
            acc.y = acc.y * inv + bb.y;
            acc.z = acc.z * inv + bb.z;
            acc.w = acc.w * inv + bb.w;
            orow[cidx] = acc;
        }
    }
}

// ================= launch =================
extern "C" void kernel_launch(void* const* d_in, const int* in_sizes, int n_in,
                              void* d_out, int out_size)
{
    const float* x  = (const float*)d_in[0];
    const float* Wq = (const float*)d_in[1];
    const float* bq = (const float*)d_in[2];
    const float* Wk = (const float*)d_in[3];
    const float* Wv = (const float*)d_in[5];
    const float* bv = (const float*)d_in[6];
    const float* Wo = (const float*)d_in[7];
    const float* bo = (const float*)d_in[8];
    float* out = (float*)d_out;

    float *xp, *A, *Aq, *Ak, *bqA, *v, *bvo;
    float *WqT, *WvT, *WoT, *WcT, *L1, *L2, *xa, *AFo;
    cudaGetSymbolAddress((void**)&xp,  g_xp);
    cudaGetSymbolAddress((void**)&A,   g_A);
    cudaGetSymbolAddress((void**)&Aq,  g_Aq);
    cudaGetSymbolAddress((void**)&Ak,  g_Ak);
    cudaGetSymbolAddress((void**)&bqA, g_bqA);
    cudaGetSymbolAddress((void**)&v,   g_v);
    cudaGetSymbolAddress((void**)&bvo, g_bvo);
    cudaGetSymbolAddress((void**)&WqT, g_WqT);
    cudaGetSymbolAddress((void**)&WvT, g_WvT);
    cudaGetSymbolAddress((void**)&WoT, g_WoT);
    cudaGetSymbolAddress((void**)&WcT, g_WcT);
    cudaGetSymbolAddress((void**)&L1,  g_L1);
    cudaGetSymbolAddress((void**)&L2,  g_L2);
    cudaGetSymbolAddress((void**)&xa,  g_xa);
    cudaGetSymbolAddress((void**)&AFo, g_AFo);

    static int init_done = 0;
    if (!init_done) {
        cudaFuncSetAttribute(gemm_nn,         cudaFuncAttributeMaxDynamicSharedMemorySize, GEMM_SMEM);
        cudaFuncSetAttribute(logits12_kernel, cudaFuncAttributeMaxDynamicSharedMemorySize, L12_SMEM);
        init_done = 1;
    }

    // 1. prep: transposes + v + bvo
    prep_kernel<<<dim3(16, 16, 4), dim3(32, 8)>>>(Wq, Wv, Wo, bq, bv, WqT, WvT, WoT, v, bvo);
    // 2. pool + bqA
    pool_bqa_kernel<<<1024, 512>>>(x, v, xp, bqA);
    // 3. A = xp@WqT + bq   AND   WcT = WvT@WoT   (one launch, 192 blocks)
    gemm_nn<<<192, 256, GEMM_SMEM>>>(xp, WqT, bq, A, WvT, WoT, nullptr, WcT, 128);
    // 4. Aq = A@Wq ; Ak = A@Wk (256 blocks)
    gemm_nn<<<256, 256, GEMM_SMEM>>>(A, Wq, nullptr, Aq, A, Wk, nullptr, Ak, 128);
    // 5. logits (L1 scaled+bqA, L2 scaled)
    logits12_kernel<<<dim3(8, 64), 256, L12_SMEM>>>(Aq, Ak, bqA, x, L1, L2);
    // 6. softmax over n for L2
    softmax_rows<<<1024, 256>>>(L2);
    // 7. xa = P2 @ x
    xa_kernel<<<dim3(4, 64), 256>>>(L2, x, xa);
    // 8. AFo = xa@WcT + bvo
    gemm_nn<<<128, 256, GEMM_SMEM>>>(xa, WcT, bvo, AFo, xa, WcT, bvo, AFo, 128);
    // 9. final combine
    final_kernel<<<dim3(16, 64), 512>>>(L1, AFo, bo, out);
}

// round 10
// speedup vs baseline: 1.0163x; 1.0163x over previous
#include <cuda_runtime.h>
#include <math.h>
#include <stdint.h>

#define Cn 512
#define Bn 64
#define Nn 1024
#define Mn 16
#define SCALE 0.04419417382415922f   // 512^-0.5

// ---------------- scratch (allocation-free) ----------------
__device__ float g_xp  [1024 * 512];    // pooled x        [B*M, C]
__device__ float g_A   [1024 * 512];    // agents          [B*M, C]
__device__ float g_Aq  [1024 * 512];    // A @ Wq
__device__ float g_Ak  [1024 * 512];    // A @ Wk
__device__ float g_bqA [1024];          // bq . A
__device__ float g_bvo [512];           // Wo . bv
__device__ float g_WqT [512 * 512];
__device__ float g_WvT [512 * 512];
__device__ float g_WoT [512 * 512];
__device__ float g_WcT [512 * 512];     // (Wo@Wv)^T = WvT @ WoT
__device__ float g_L2  [64 * 16 * 1024];// stage-2 logits
__device__ float g_L1  [64 * 1024 * 16];// stage-1 logits (scaled, +bqA)
__device__ float g_xa  [1024 * 512];    // P2 @ x
__device__ float g_AFo [1024 * 512];    // xa @ WcT + bvo

__device__ __forceinline__ uint32_t smem_u32(const void* p) {
    return (uint32_t)__cvta_generic_to_shared(p);
}
__device__ __forceinline__ void cp_async16(uint32_t s, const void* g) {
    asm volatile("cp.async.cg.shared.global [%0], [%1], 16;" :: "r"(s), "l"(g));
}

// ================= batched 512x512 transpose (Wq, Wv, Wo) =================
__global__ void transpose3(const float* __restrict__ Wq, const float* __restrict__ Wv,
                           const float* __restrict__ Wo, float* __restrict__ WqT,
                           float* __restrict__ WvT, float* __restrict__ WoT)
{
    __shared__ float t[32][33];
    const float* s; float* d;
    if (blockIdx.z == 0)      { s = Wq; d = WqT; }
    else if (blockIdx.z == 1) { s = Wv; d = WvT; }
    else                      { s = Wo; d = WoT; }
    const int x  = blockIdx.x * 32 + threadIdx.x;
    const int y0 = blockIdx.y * 32 + threadIdx.y;
#pragma unroll
    for (int j = 0; j < 32; j += 8)
        t[threadIdx.y + j][threadIdx.x] = s[(size_t)(y0 + j) * Cn + x];
    __syncthreads();
    const int ox  = blockIdx.y * 32 + threadIdx.x;
    const int oy0 = blockIdx.x * 32 + threadIdx.y;
#pragma unroll
    for (int j = 0; j < 32; j += 8)
        d[(size_t)(oy0 + j) * Cn + ox] = t[threadIdx.x][threadIdx.y + j];
}

// ================= pooling =================
__global__ void pool_x_kernel(const float* __restrict__ x, float* __restrict__ xp)
{
    int bm = blockIdx.x;
    int c  = threadIdx.x;
    const float* base = x + (size_t)bm * 64 * Cn + c;
    float s = 0.f;
#pragma unroll 8
    for (int t = 0; t < 64; t++) s += base[(size_t)t * Cn];
    xp[(size_t)bm * Cn + c] = s * (1.0f / 64.0f);
}

// ================= NN GEMM: Y[r,n] = sum_k X[r,k] W[k,n] (+bias) =================
// K=512. Tile 64x64, BK=32, 3-stage cp.async, 256 thr, 4x4/thread, float4 inner.
// dual-W: blocks bx < nsplit use (W0,Y0,n0=bx*64), else (W1,Y1,n0=(bx-nsplit)*64)
#define XS_FLOATS (64 * 36)          // 2304
#define WS_FLOATS (32 * 68)          // 2176
#define STAGE_FLOATS (XS_FLOATS + WS_FLOATS)  // 4480
#define GEMM_SMEM (3 * STAGE_FLOATS * 4)      // 53760

__global__ __launch_bounds__(256)
void gemm_nn(const float* __restrict__ X, const float* __restrict__ W0,
             const float* __restrict__ W1, const float* __restrict__ bias,
             float* __restrict__ Y0, float* __restrict__ Y1, int nsplit)
{
    extern __shared__ float sm[];
    const int tid = threadIdx.x;
    const int tx = tid & 15, ty = tid >> 4;
    const int r0 = blockIdx.y * 64;
    const float* W; float* Y; int n0;
    if ((int)blockIdx.x < nsplit) { W = W0; Y = Y0; n0 = blockIdx.x * 64; }
    else                          { W = W1; Y = Y1; n0 = (blockIdx.x - nsplit) * 64; }

    const int xlr = tid >> 2, xlk = (tid & 3) * 8;
    const int wwk = tid >> 3, wwn = (tid & 7) * 8;
    const float* gX = X + (size_t)(r0 + xlr) * Cn + xlk;
    const float* gW = W + (size_t)wwk * Cn + n0 + wwn;
    const uint32_t sbase = smem_u32(sm);
    const uint32_t xdst = sbase + (uint32_t)(xlr * 36 + xlk) * 4u;
    const uint32_t wdst = sbase + (uint32_t)(XS_FLOATS + wwk * 68 + wwn) * 4u;

#define G_LOAD(ST, K0)                                                          \
    do {                                                                        \
        const uint32_t so_ = (uint32_t)(ST) * (STAGE_FLOATS * 4u);              \
        cp_async16(xdst + so_,      gX + (K0));                                 \
        cp_async16(xdst + so_ + 16, gX + (K0) + 4);                             \
        cp_async16(wdst + so_,      gW + (size_t)(K0) * Cn);                    \
        cp_async16(wdst + so_ + 16, gW + (size_t)(K0) * Cn + 4);                \
        asm volatile("cp.async.commit_group;" ::: "memory");                    \
    } while (0)

    float acc[4][4];
#pragma unroll
    for (int i = 0; i < 4; i++)
#pragma unroll
        for (int j = 0; j < 4; j++) acc[i][j] = 0.f;

    G_LOAD(0, 0);
    G_LOAD(1, 32);

#pragma unroll 1
    for (int it = 0; it < 16; it++) {
        if (it < 15) asm volatile("cp.async.wait_group 1;" ::: "memory");
        else         asm volatile("cp.async.wait_group 0;" ::: "memory");
        __syncthreads();
        if (it + 2 < 16) G_LOAD((it + 2) % 3, (it + 2) * 32);

        const float* Xst = sm + (it % 3) * STAGE_FLOATS;
        const float* Wst = Xst + XS_FLOATS;
#pragma unroll
        for (int k4 = 0; k4 < 8; k4++) {
            float aa[4][4], bb[4][4];
#pragma unroll
            for (int i = 0; i < 4; i++) {
                float4 a = *(const float4*)(Xst + (ty * 4 + i) * 36 + k4 * 4);
                aa[i][0] = a.x; aa[i][1] = a.y; aa[i][2] = a.z; aa[i][3] = a.w;
            }
#pragma unroll
            for (int q = 0; q < 4; q++) {
                float4 b = *(const float4*)(Wst + (k4 * 4 + q) * 68 + tx * 4);
                bb[q][0] = b.x; bb[q][1] = b.y; bb[q][2] = b.z; bb[q][3] = b.w;
            }
#pragma unroll
            for (int i = 0; i < 4; i++)
#pragma unroll
                for (int j = 0; j < 4; j++)
#pragma unroll
                    for (int q = 0; q < 4; q++)
                        acc[i][j] = fmaf(aa[i][q], bb[q][j], acc[i][j]);
        }
    }
#undef G_LOAD

    float4 bi = make_float4(0.f, 0.f, 0.f, 0.f);
    if (bias) bi = *(const float4*)(bias + n0 + tx * 4);
#pragma unroll
    for (int i = 0; i < 4; i++) {
        float4 o;
        o.x = acc[i][0] + bi.x; o.y = acc[i][1] + bi.y;
        o.z = acc[i][2] + bi.z; o.w = acc[i][3] + bi.w;
        *(float4*)(Y + (size_t)(r0 + ty * 4 + i) * Cn + n0 + tx * 4) = o;
    }
}

// ================= rowdot: dst[r] = src[r,:] . vec (rows of 512) =================
__global__ void rowdot_kernel(const float* __restrict__ src, const float* __restrict__ vec,
                              float* __restrict__ dst)
{
    const int row  = blockIdx.x * 8 + (threadIdx.x >> 5);
    const int lane = threadIdx.x & 31;
    const float* sr = src + (size_t)row * Cn;
    float s = 0.f;
#pragma unroll
    for (int k = 0; k < 16; k++) s += sr[lane + 32 * k] * __ldg(&vec[lane + 32 * k]);
#pragma unroll
    for (int off = 16; off > 0; off >>= 1) s += __shfl_xor_sync(0xffffffffu, s, off);
    if (lane == 0) dst[row] = s;
}

// ================= fused logits: L1[b,n,m], L2[b,m,n] in one x pass =================
#define L12_SMEM (2 * 16 * 512 * 4 + 64 * 128 * 4 + 64)
__global__ __launch_bounds__(256)
void logits12_kernel(const float* __restrict__ Aq, const float* __restrict__ Ak,
                     const float* __restrict__ bqA, const float* __restrict__ x,
                     float* __restrict__ L1, float* __restrict__ L2)
{
    extern __shared__ float sm[];
    float* Aq_s = sm;                 // [16][512]
    float* Ak_s = sm + 8192;          // [16][512]
    float* xs   = sm + 16384;         // [64][128] k-major
    float* bq_s = sm + 24576;         // [16]
    const int b   = blockIdx.y;
    const int n0  = blockIdx.x * 128;
    const int tid = threadIdx.x;
    const int mi  = tid >> 6;
    const int ni  = tid & 63;
    const int lnr = tid >> 1;
    const int le  = tid & 1;

    {
        const float4* sq = (const float4*)(Aq + (size_t)b * 16 * Cn);
        const float4* sk = (const float4*)(Ak + (size_t)b * 16 * Cn);
        float4* dq = (float4*)Aq_s;
        float4* dk = (float4*)Ak_s;
        for (int i = tid; i < 2048; i += 256) { dq[i] = sq[i]; dk[i] = sk[i]; }
        if (tid < 16) bq_s[tid] = bqA[b * 16 + tid];
    }

    float acc1[4][2] = {}, acc2[4][2] = {};
    for (int kt = 0; kt < 8; kt++) {
        __syncthreads();
        const float* gx = x + ((size_t)b * Nn + n0 + lnr) * Cn + kt * 64 + le * 32;
#pragma unroll
        for (int f = 0; f < 8; f++) {
            float4 v = *(const float4*)(gx + f * 4);
            const int k = le * 32 + f * 4;
            xs[(k + 0) * 128 + lnr] = v.x;
            xs[(k + 1) * 128 + lnr] = v.y;
            xs[(k + 2) * 128 + lnr] = v.z;
            xs[(k + 3) * 128 + lnr] = v.w;
        }
        __syncthreads();
        const float* aqb = Aq_s + (size_t)mi * 4 * Cn + kt * 64;
        const float* akb = Ak_s + (size_t)mi * 4 * Cn + kt * 64;
#pragma unroll 8
        for (int k = 0; k < 64; k++) {
            float2 xv = *(const float2*)(xs + k * 128 + 2 * ni);
#pragma unroll
            for (int j = 0; j < 4; j++) {
                float aq = aqb[j * Cn + k];
                float ak = akb[j * Cn + k];
                acc1[j][0] = fmaf(aq, xv.x, acc1[j][0]);
                acc1[j][1] = fmaf(aq, xv.y, acc1[j][1]);
                acc2[j][0] = fmaf(ak, xv.x, acc2[j][0]);
                acc2[j][1] = fmaf(ak, xv.y, acc2[j][1]);
            }
        }
    }
#pragma unroll
    for (int j = 0; j < 4; j++) {
        float2 o = make_float2(acc2[j][0] * SCALE, acc2[j][1] * SCALE);
        *(float2*)(L2 + ((size_t)b * 16 + mi * 4 + j) * Nn + n0 + 2 * ni) = o;
    }
    {
        float4 o0, o1;
        float* p0 = (float*)&o0; float* p1 = (float*)&o1;
#pragma unroll
        for (int j = 0; j < 4; j++) {
            p0[j] = (acc1[j][0] + bq_s[mi * 4 + j]) * SCALE;
            p1[j] = (acc1[j][1] + bq_s[mi * 4 + j]) * SCALE;
        }
        *(float4*)(L1 + ((size_t)b * Nn + n0 + 2 * ni)     * 16 + mi * 4) = o0;
        *(float4*)(L1 + ((size_t)b * Nn + n0 + 2 * ni + 1) * 16 + mi * 4) = o1;
    }
}

// ================= xa = softmax_n(L2) @ x (softmax fused) =================
#define XA_SMEM (16 * 1024 * 4 + 64 * 132 * 4)
__global__ __launch_bounds__(256)
void xa_kernel(const float* __restrict__ L2, const float* __restrict__ x,
               float* __restrict__ xa)
{
    extern __shared__ float sm[];
    float* ps = sm;
    float* xs = sm + 16384;
    const int b   = blockIdx.y;
    const int c0  = blockIdx.x * 128;
    const int tid = threadIdx.x;
    const int warp = tid >> 5, lane = tid & 31;
    const int mi  = tid >> 6;
    const int ci  = tid & 63;
    const int lnr = tid >> 3;

    for (int m = warp; m < 16; m += 8) {
        const float* row = L2 + ((size_t)b * 16 + m) * Nn;
        float mx = -INFINITY;
#pragma unroll
        for (int i = 0; i < 32; i++) mx = fmaxf(mx, __ldg(row + lane + 32 * i));
#pragma unroll
        for (int off = 16; off > 0; off >>= 1)
            mx = fmaxf(mx, __shfl_xor_sync(0xffffffffu, mx, off));
        float sum = 0.f;
#pragma unroll
        for (int i = 0; i < 32; i++) {
            float e = __expf(__ldg(row + lane + 32 * i) - mx);
            ps[m * Nn + lane + 32 * i] = e;
            sum += e;
        }
#pragma unroll
        for (int off = 16; off > 0; off >>= 1)
            sum += __shfl_xor_sync(0xffffffffu, sum, off);
        const float inv = 1.0f / sum;
#pragma unroll
        for (int i = 0; i < 32; i++) ps[m * Nn + lane + 32 * i] *= inv;
    }

    float acc[4][2] = {};
    for (int nt = 0; nt < 16; nt++) {
        __syncthreads();
#pragma unroll
        for (int h = 0; h < 2; h++) {
            const int n = lnr + h * 32;
            const float* gx = x + ((size_t)b * Nn + nt * 64 + n) * Cn + c0;
#pragma unroll
            for (int q = 0; q < 4; q++) {
                const int cc = ((tid & 7) + q * 8) * 4;
                *(float4*)(xs + n * 132 + cc) = *(const float4*)(gx + cc);
            }
        }
        __syncthreads();
        const float* pb = ps + (size_t)mi * 4 * Nn + nt * 64;
#pragma unroll 8
        for (int n = 0; n < 64; n++) {
            float2 xv = *(const float2*)(xs + n * 132 + 2 * ci);
#pragma unroll
            for (int j = 0; j < 4; j++) {
                float p = pb[j * Nn + n];
                acc[j][0] = fmaf(p, xv.x, acc[j][0]);
                acc[j][1] = fmaf(p, xv.y, acc[j][1]);
            }
        }
    }
#pragma unroll
    for (int j = 0; j < 4; j++)
        *(float2*)(xa + ((size_t)b * 16 + mi * 4 + j) * Cn + c0 + 2 * ci)
            = make_float2(acc[j][0], acc[j][1]);
}

// ================= final (float4 inner loop) =================
__global__ __launch_bounds__(512)
void final_kernel(const float* __restrict__ L1, const float* __restrict__ AFo,
                  const float* __restrict__ bo, float* __restrict__ out)
{
    __shared__ float4 afo4[Mn * 128];    // 32 KB
    __shared__ float  l1s[64 * 16];      // 4 KB
    __shared__ float4 bo4[128];          // 2 KB
    const int b    = blockIdx.y;
    const int n0   = blockIdx.x * 64;
    const int tid  = threadIdx.x;
    const int warp = tid >> 5;
    const int lane = tid & 31;

    {
        const float4* s = (const float4*)(AFo + (size_t)b * Mn * Cn);
        for (int i = tid; i < 2048; i += 512) afo4[i] = s[i];
        const float4* sl = (const float4*)(L1 + ((size_t)b * Nn + n0) * 16);
        if (tid < 256) ((float4*)l1s)[tid] = sl[tid];
        if (tid < 128) bo4[tid] = ((const float4*)bo)[tid];
    }
    __syncthreads();

#pragma unroll
    for (int t = 0; t < 4; t++) {
        const int tok = warp * 4 + t;
        float lg[16];
#pragma unroll
        for (int m = 0; m < Mn; m++) lg[m] = l1s[tok * 16 + m];
        float mx = lg[0];
#pragma unroll
        for (int m = 1; m < Mn; m++) mx = fmaxf(mx, lg[m]);
        float s = 0.f;
#pragma unroll
        for (int m = 0; m < Mn; m++) { lg[m] = __expf(lg[m] - mx); s += lg[m]; }
        const float inv = 1.0f / s;

        float4* orow = (float4*)(out + ((size_t)b * Nn + n0 + tok) * Cn);
#pragma unroll
        for (int kc = 0; kc < 4; kc++) {
            const int cidx = kc * 32 + lane;
            float4 acc = make_float4(0.f, 0.f, 0.f, 0.f);
#pragma unroll
            for (int m = 0; m < Mn; m++) {
                float4 f = afo4[m * 128 + cidx];
                acc.x = fmaf(lg[m], f.x, acc.x);
                acc.y = fmaf(lg[m], f.y, acc.y);
                acc.z = fmaf(lg[m], f.z, acc.z);
                acc.w = fmaf(lg[m], f.w, acc.w);
            }
            float4 bb = bo4[cidx];
            acc.x = acc.x * inv + bb.x;
            acc.y = acc.y * inv + bb.y;
            acc.z = acc.z * inv + bb.z;
            acc.w = acc.w * inv + bb.w;
            orow[cidx] = acc;
        }
    }
}

// ================= launch =================
extern "C" void kernel_launch(void* const* d_in, const int* in_sizes, int n_in,
                              void* d_out, int out_size)
{
    const float* x  = (const float*)d_in[0];
    const float* Wq = (const float*)d_in[1];
    const float* bq = (const float*)d_in[2];
    const float* Wk = (const float*)d_in[3];
    const float* Wv = (const float*)d_in[5];
    const float* bv = (const float*)d_in[6];
    const float* Wo = (const float*)d_in[7];
    const float* bo = (const float*)d_in[8];
    float* out = (float*)d_out;

    float *xp, *A, *Aq, *Ak, *bqA, *bvo, *WqT, *WvT, *WoT, *WcT, *L1, *L2, *xa, *AFo;
    cudaGetSymbolAddress((void**)&xp,  g_xp);
    cudaGetSymbolAddress((void**)&A,   g_A);
    cudaGetSymbolAddress((void**)&Aq,  g_Aq);
    cudaGetSymbolAddress((void**)&Ak,  g_Ak);
    cudaGetSymbolAddress((void**)&bqA, g_bqA);
    cudaGetSymbolAddress((void**)&bvo, g_bvo);
    cudaGetSymbolAddress((void**)&WqT, g_WqT);
    cudaGetSymbolAddress((void**)&WvT, g_WvT);
    cudaGetSymbolAddress((void**)&WoT, g_WoT);
    cudaGetSymbolAddress((void**)&WcT, g_WcT);
    cudaGetSymbolAddress((void**)&L1,  g_L1);
    cudaGetSymbolAddress((void**)&L2,  g_L2);
    cudaGetSymbolAddress((void**)&xa,  g_xa);
    cudaGetSymbolAddress((void**)&AFo, g_AFo);

    static int attr_set = 0;
    if (!attr_set) {
        cudaFuncSetAttribute(gemm_nn,         cudaFuncAttributeMaxDynamicSharedMemorySize, GEMM_SMEM);
        cudaFuncSetAttribute(logits12_kernel, cudaFuncAttributeMaxDynamicSharedMemorySize, L12_SMEM);
        cudaFuncSetAttribute(xa_kernel,       cudaFuncAttributeMaxDynamicSharedMemorySize, XA_SMEM);
        attr_set = 1;
    }

    // independent preprocessing
    transpose3<<<dim3(16, 16, 3), dim3(32, 8)>>>(Wq, Wv, Wo, WqT, WvT, WoT);
    pool_x_kernel<<<1024, 512>>>(x, xp);
    rowdot_kernel<<<64, 256>>>(Wo, bv, bvo);                        // bvo = Wo . bv
    gemm_nn<<<dim3(8, 8),  256, GEMM_SMEM>>>(WvT, WoT, WoT, nullptr, WcT, WcT, 8);  // WcT = WvT@WoT

    // main chain
    gemm_nn<<<dim3(8, 16), 256, GEMM_SMEM>>>(xp, WqT, WqT, bq, A, A, 8);            // A = xp@Wq^T + bq
    gemm_nn<<<dim3(16, 16), 256, GEMM_SMEM>>>(A, Wq, Wk, nullptr, Aq, Ak, 8);       // Aq, Ak
    rowdot_kernel<<<128, 256>>>(A, bq, bqA);                        // bqA = A . bq

    logits12_kernel<<<dim3(8, 64), 256, L12_SMEM>>>(Aq, Ak, bqA, x, L1, L2);
    xa_kernel<<<dim3(4, 64), 256, XA_SMEM>>>(L2, x, xa);
    gemm_nn<<<dim3(8, 16), 256, GEMM_SMEM>>>(xa, WcT, WcT, bvo, AFo, AFo, 8);       // AFo = xa@WcT + bvo
    final_kernel<<<dim3(16, 64), 512>>>(L1, AFo, bo, out);
}

// round 11
// speedup vs baseline: 2.3616x; 2.3237x over previous
#include <cuda_runtime.h>
#include <math.h>
#include <stdint.h>

#define Cn 512
#define Bn 64
#define Nn 1024
#define Mn 16
#define SCALE 0.04419417382415922f   // 512^-0.5

// ---------------- scratch (allocation-free) ----------------
__device__ float g_xp  [1024 * 512];    // pooled x        [B*M, C]
__device__ float g_A   [1024 * 512];    // agents          [B*M, C]
__device__ float g_Aq  [1024 * 512];    // A @ Wq
__device__ float g_Ak  [1024 * 512];    // A @ Wk
__device__ float g_bqA [1024];          // bq . A
__device__ float g_bvo [512];           // Wo . bv
__device__ float g_WqT [512 * 512];
__device__ float g_WvT [512 * 512];
__device__ float g_WoT [512 * 512];
__device__ float g_WcT [512 * 512];     // (Wo@Wv)^T = WvT @ WoT
__device__ float g_L2  [64 * 16 * 1024];// stage-2 logits
__device__ float g_L1  [64 * 1024 * 16];// stage-1 logits (scaled, +bqA)
__device__ float g_xa  [1024 * 512];    // P2 @ x
__device__ float g_AFo [1024 * 512];    // xa @ WcT + bvo

__device__ __forceinline__ uint32_t smem_u32(const void* p) {
    return (uint32_t)__cvta_generic_to_shared(p);
}
__device__ __forceinline__ void cp_async16(uint32_t s, const void* g) {
    asm volatile("cp.async.cg.shared.global [%0], [%1], 16;" :: "r"(s), "l"(g));
}

// ================= batched 512x512 transpose (Wq, Wv, Wo) =================
__global__ void transpose3(const float* __restrict__ Wq, const float* __restrict__ Wv,
                           const float* __restrict__ Wo, float* __restrict__ WqT,
                           float* __restrict__ WvT, float* __restrict__ WoT)
{
    __shared__ float t[32][33];
    const float* s; float* d;
    if (blockIdx.z == 0)      { s = Wq; d = WqT; }
    else if (blockIdx.z == 1) { s = Wv; d = WvT; }
    else                      { s = Wo; d = WoT; }
    const int x  = blockIdx.x * 32 + threadIdx.x;
    const int y0 = blockIdx.y * 32 + threadIdx.y;
#pragma unroll
    for (int j = 0; j < 32; j += 8)
        t[threadIdx.y + j][threadIdx.x] = s[(size_t)(y0 + j) * Cn + x];
    __syncthreads();
    const int ox  = blockIdx.y * 32 + threadIdx.x;
    const int oy0 = blockIdx.x * 32 + threadIdx.y;
#pragma unroll
    for (int j = 0; j < 32; j += 8)
        d[(size_t)(oy0 + j) * Cn + ox] = t[threadIdx.x][threadIdx.y + j];
}

// ================= pooling =================
__global__ void pool_x_kernel(const float* __restrict__ x, float* __restrict__ xp)
{
    int bm = blockIdx.x;
    int c  = threadIdx.x;
    const float* base = x + (size_t)bm * 64 * Cn + c;
    float s = 0.f;
#pragma unroll 8
    for (int t = 0; t < 64; t++) s += base[(size_t)t * Cn];
    xp[(size_t)bm * Cn + c] = s * (1.0f / 64.0f);
}

// ================= NN GEMM: Y[r,n] = sum_k X[r,k] W[k,n] (+bias) =================
// K=512. Tile 64x64, BK=32, 3-stage cp.async, 256 thr, 4x4/thread, float4 inner.
// dual-W: blocks bx < nsplit use (W0,Y0,n0=bx*64), else (W1,Y1,n0=(bx-nsplit)*64)
#define XS_FLOATS (64 * 36)          // 2304
#define WS_FLOATS (32 * 68)          // 2176
#define STAGE_FLOATS (XS_FLOATS + WS_FLOATS)  // 4480
#define GEMM_SMEM (3 * STAGE_FLOATS * 4)      // 53760

__global__ __launch_bounds__(256)
void gemm_nn(const float* __restrict__ X, const float* __restrict__ W0,
             const float* __restrict__ W1, const float* __restrict__ bias,
             float* __restrict__ Y0, float* __restrict__ Y1, int nsplit)
{
    extern __shared__ float sm[];
    const int tid = threadIdx.x;
    const int tx = tid & 15, ty = tid >> 4;
    const int r0 = blockIdx.y * 64;
    const float* W; float* Y; int n0;
    if ((int)blockIdx.x < nsplit) { W = W0; Y = Y0; n0 = blockIdx.x * 64; }
    else                          { W = W1; Y = Y1; n0 = (blockIdx.x - nsplit) * 64; }

    const int xlr = tid >> 2, xlk = (tid & 3) * 8;
    const int wwk = tid >> 3, wwn = (tid & 7) * 8;
    const float* gX = X + (size_t)(r0 + xlr) * Cn + xlk;
    const float* gW = W + (size_t)wwk * Cn + n0 + wwn;
    const uint32_t sbase = smem_u32(sm);
    const uint32_t xdst = sbase + (uint32_t)(xlr * 36 + xlk) * 4u;
    const uint32_t wdst = sbase + (uint32_t)(XS_FLOATS + wwk * 68 + wwn) * 4u;

#define G_LOAD(ST, K0)                                                          \
    do {                                                                        \
        const uint32_t so_ = (uint32_t)(ST) * (STAGE_FLOATS * 4u);              \
        cp_async16(xdst + so_,      gX + (K0));                                 \
        cp_async16(xdst + so_ + 16, gX + (K0) + 4);                             \
        cp_async16(wdst + so_,      gW + (size_t)(K0) * Cn);                    \
        cp_async16(wdst + so_ + 16, gW + (size_t)(K0) * Cn + 4);                \
        asm volatile("cp.async.commit_group;" ::: "memory");                    \
    } while (0)

    float acc[4][4];
#pragma unroll
    for (int i = 0; i < 4; i++)
#pragma unroll
        for (int j = 0; j < 4; j++) acc[i][j] = 0.f;

    G_LOAD(0, 0);
    G_LOAD(1, 32);

#pragma unroll 1
    for (int it = 0; it < 16; it++) {
        if (it < 15) asm volatile("cp.async.wait_group 1;" ::: "memory");
        else         asm volatile("cp.async.wait_group 0;" ::: "memory");
        __syncthreads();
        if (it + 2 < 16) G_LOAD((it + 2) % 3, (it + 2) * 32);

        const float* Xst = sm + (it % 3) * STAGE_FLOATS;
        const float* Wst = Xst + XS_FLOATS;
#pragma unroll
        for (int k4 = 0; k4 < 8; k4++) {
            float aa[4][4], bb[4][4];
#pragma unroll
            for (int i = 0; i < 4; i++) {
                float4 a = *(const float4*)(Xst + (ty * 4 + i) * 36 + k4 * 4);
                aa[i][0] = a.x; aa[i][1] = a.y; aa[i][2] = a.z; aa[i][3] = a.w;
            }
#pragma unroll
            for (int q = 0; q < 4; q++) {
                float4 b = *(const float4*)(Wst + (k4 * 4 + q) * 68 + tx * 4);
                bb[q][0] = b.x; bb[q][1] = b.y; bb[q][2] = b.z; bb[q][3] = b.w;
            }
#pragma unroll
            for (int i = 0; i < 4; i++)
#pragma unroll
                for (int j = 0; j < 4; j++)
#pragma unroll
                    for (int q = 0; q < 4; q++)
                        acc[i][j] = fmaf(aa[i][q], bb[q][j], acc[i][j]);
        }
    }
#undef G_LOAD

    float4 bi = make_float4(0.f, 0.f, 0.f, 0.f);
    if (bias) bi = *(const float4*)(bias + n0 + tx * 4);
#pragma unroll
    for (int i = 0; i < 4; i++) {
        float4 o;
        o.x = acc[i][0] + bi.x; o.y = acc[i][1] + bi.y;
        o.z = acc[i][2] + bi.z; o.w = acc[i][3] + bi.w;
        *(float4*)(Y + (size_t)(r0 + ty * 4 + i) * Cn + n0 + tx * 4) = o;
    }
}

// ================= rowdot: dst[r] = src[r,:] . vec (rows of 512) =================
__global__ void rowdot_kernel(const float* __restrict__ src, const float* __restrict__ vec,
                              float* __restrict__ dst)
{
    const int row  = blockIdx.x * 8 + (threadIdx.x >> 5);
    const int lane = threadIdx.x & 31;
    const float* sr = src + (size_t)row * Cn;
    float s = 0.f;
#pragma unroll
    for (int k = 0; k < 16; k++) s += sr[lane + 32 * k] * __ldg(&vec[lane + 32 * k]);
#pragma unroll
    for (int off = 16; off > 0; off >>= 1) s += __shfl_xor_sync(0xffffffffu, s, off);
    if (lane == 0) dst[row] = s;
}

// ================= fused logits: L1[b,n,m], L2[b,m,n] in one x pass =================
#define L12_SMEM (2 * 16 * 512 * 4 + 64 * 128 * 4 + 64)
__global__ __launch_bounds__(256)
void logits12_kernel(const float* __restrict__ Aq, const float* __restrict__ Ak,
                     const float* __restrict__ bqA, const float* __restrict__ x,
                     float* __restrict__ L1, float* __restrict__ L2)
{
    extern __shared__ float sm[];
    float* Aq_s = sm;                 // [16][512]
    float* Ak_s = sm + 8192;          // [16][512]
    float* xs   = sm + 16384;         // [64][128] k-major
    float* bq_s = sm + 24576;         // [16]
    const int b   = blockIdx.y;
    const int n0  = blockIdx.x * 128;
    const int tid = threadIdx.x;
    const int mi  = tid >> 6;
    const int ni  = tid & 63;
    const int lnr = tid >> 1;
    const int le  = tid & 1;

    {
        const float4* sq = (const float4*)(Aq + (size_t)b * 16 * Cn);
        const float4* sk = (const float4*)(Ak + (size_t)b * 16 * Cn);
        float4* dq = (float4*)Aq_s;
        float4* dk = (float4*)Ak_s;
        for (int i = tid; i < 2048; i += 256) { dq[i] = sq[i]; dk[i] = sk[i]; }
        if (tid < 16) bq_s[tid] = bqA[b * 16 + tid];
    }

    float acc1[4][2] = {}, acc2[4][2] = {};
    for (int kt = 0; kt < 8; kt++) {
        __syncthreads();
        const float* gx = x + ((size_t)b * Nn + n0 + lnr) * Cn + kt * 64 + le * 32;
#pragma unroll
        for (int f = 0; f < 8; f++) {
            float4 v = *(const float4*)(gx + f * 4);
            const int k = le * 32 + f * 4;
            xs[(k + 0) * 128 + lnr] = v.x;
            xs[(k + 1) * 128 + lnr] = v.y;
            xs[(k + 2) * 128 + lnr] = v.z;
            xs[(k + 3) * 128 + lnr] = v.w;
        }
        __syncthreads();
        const float* aqb = Aq_s + (size_t)mi * 4 * Cn + kt * 64;
        const float* akb = Ak_s + (size_t)mi * 4 * Cn + kt * 64;
#pragma unroll 8
        for (int k = 0; k < 64; k++) {
            float2 xv = *(const float2*)(xs + k * 128 + 2 * ni);
#pragma unroll
            for (int j = 0; j < 4; j++) {
                float aq = aqb[j * Cn + k];
                float ak = akb[j * Cn + k];
                acc1[j][0] = fmaf(aq, xv.x, acc1[j][0]);
                acc1[j][1] = fmaf(aq, xv.y, acc1[j][1]);
                acc2[j][0] = fmaf(ak, xv.x, acc2[j][0]);
                acc2[j][1] = fmaf(ak, xv.y, acc2[j][1]);
            }
        }
    }
#pragma unroll
    for (int j = 0; j < 4; j++) {
        float2 o = make_float2(acc2[j][0] * SCALE, acc2[j][1] * SCALE);
        *(float2*)(L2 + ((size_t)b * 16 + mi * 4 + j) * Nn + n0 + 2 * ni) = o;
    }
    {
        float4 o0, o1;
        float* p0 = (float*)&o0; float* p1 = (float*)&o1;
#pragma unroll
        for (int j = 0; j < 4; j++) {
            p0[j] = (acc1[j][0] + bq_s[mi * 4 + j]) * SCALE;
            p1[j] = (acc1[j][1] + bq_s[mi * 4 + j]) * SCALE;
        }
        *(float4*)(L1 + ((size_t)b * Nn + n0 + 2 * ni)     * 16 + mi * 4) = o0;
        *(float4*)(L1 + ((size_t)b * Nn + n0 + 2 * ni + 1) * 16 + mi * 4) = o1;
    }
}

// ================= xa = softmax_n(L2) @ x (softmax fused) =================
#define XA_SMEM (16 * 1024 * 4 + 64 * 132 * 4)
__global__ __launch_bounds__(256)
void xa_kernel(const float* __restrict__ L2, const float* __restrict__ x,
               float* __restrict__ xa)
{
    extern __shared__ float sm[];
    float* ps = sm;
    float* xs = sm + 16384;
    const int b   = blockIdx.y;
    const int c0  = blockIdx.x * 128;
    const int tid = threadIdx.x;
    const int warp = tid >> 5, lane = tid & 31;
    const int mi  = tid >> 6;
    const int ci  = tid & 63;
    const int lnr = tid >> 3;

    for (int m = warp; m < 16; m += 8) {
        const float* row = L2 + ((size_t)b * 16 + m) * Nn;
        float mx = -INFINITY;
#pragma unroll
        for (int i = 0; i < 32; i++) mx = fmaxf(mx, __ldg(row + lane + 32 * i));
#pragma unroll
        for (int off = 16; off > 0; off >>= 1)
            mx = fmaxf(mx, __shfl_xor_sync(0xffffffffu, mx, off));
        float sum = 0.f;
#pragma unroll
        for (int i = 0; i < 32; i++) {
            float e = __expf(__ldg(row + lane + 32 * i) - mx);
            ps[m * Nn + lane + 32 * i] = e;
            sum += e;
        }
#pragma unroll
        for (int off = 16; off > 0; off >>= 1)
            sum += __shfl_xor_sync(0xffffffffu, sum, off);
        const float inv = 1.0f / sum;
#pragma unroll
        for (int i = 0; i < 32; i++) ps[m * Nn + lane + 32 * i] *= inv;
    }

    float acc[4][2] = {};
    for (int nt = 0; nt < 16; nt++) {
        __syncthreads();
#pragma unroll
        for (int h = 0; h < 2; h++) {
            const int n = lnr + h * 32;
            const float* gx = x + ((size_t)b * Nn + nt * 64 + n) * Cn + c0;
#pragma unroll
            for (int q = 0; q < 4; q++) {
                const int cc = ((tid & 7) + q * 8) * 4;
                *(float4*)(xs + n * 132 + cc) = *(const float4*)(gx + cc);
            }
        }
        __syncthreads();
        const float* pb = ps + (size_t)mi * 4 * Nn + nt * 64;
#pragma unroll 8
        for (int n = 0; n < 64; n++) {
            float2 xv = *(const float2*)(xs + n * 132 + 2 * ci);
#pragma unroll
            for (int j = 0; j < 4; j++) {
                float p = pb[j * Nn + n];
                acc[j][0] = fmaf(p, xv.x, acc[j][0]);
                acc[j][1] = fmaf(p, xv.y, acc[j][1]);
            }
        }
    }
#pragma unroll
    for (int j = 0; j < 4; j++)
        *(float2*)(xa + ((size_t)b * 16 + mi * 4 + j) * Cn + c0 + 2 * ci)
            = make_float2(acc[j][0], acc[j][1]);
}

// ================= final: float4 inner, token loop NOT unrolled (bounded regs) =================
__global__ __launch_bounds__(512)
void final_kernel(const float* __restrict__ L1, const float* __restrict__ AFo,
                  const float* __restrict__ bo, float* __restrict__ out)
{
    __shared__ float4 afo4[Mn * 128];    // 32 KB
    __shared__ float  l1s[64 * 16];      // 4 KB
    __shared__ float4 bo4[128];          // 2 KB
    const int b    = blockIdx.y;
    const int n0   = blockIdx.x * 64;
    const int tid  = threadIdx.x;
    const int warp = tid >> 5;
    const int lane = tid & 31;

    {
        const float4* s = (const float4*)(AFo + (size_t)b * Mn * Cn);
        for (int i = tid; i < 2048; i += 512) afo4[i] = s[i];
        const float4* sl = (const float4*)(L1 + ((size_t)b * Nn + n0) * 16);
        if (tid < 256) ((float4*)l1s)[tid] = sl[tid];
        if (tid < 128) bo4[tid] = ((const float4*)bo)[tid];
    }
    __syncthreads();

#pragma unroll 1
    for (int t = 0; t < 4; t++) {
        const int tok = warp * 4 + t;
        float lg[16];
#pragma unroll
        for (int m = 0; m < Mn; m++) lg[m] = l1s[tok * 16 + m];
        float mx = lg[0];
#pragma unroll
        for (int m = 1; m < Mn; m++) mx = fmaxf(mx, lg[m]);
        float s = 0.f;
#pragma unroll
        for (int m = 0; m < Mn; m++) { lg[m] = __expf(lg[m] - mx); s += lg[m]; }
        const float inv = 1.0f / s;

        float4* orow = (float4*)(out + ((size_t)b * Nn + n0 + tok) * Cn);
#pragma unroll 1
        for (int kc = 0; kc < 4; kc++) {
            const int cidx = kc * 32 + lane;
            float4 acc = make_float4(0.f, 0.f, 0.f, 0.f);
#pragma unroll
            for (int m = 0; m < Mn; m++) {
                float4 f = afo4[m * 128 + cidx];
                acc.x = fmaf(lg[m], f.x, acc.x);
                acc.y = fmaf(lg[m], f.y, acc.y);
                acc.z = fmaf(lg[m], f.z, acc.z);
                acc.w = fmaf(lg[m], f.w, acc.w);
            }
            float4 bb = bo4[cidx];
            acc.x = acc.x * inv + bb.x;
            acc.y = acc.y * inv + bb.y;
            acc.z = acc.z * inv + bb.z;
            acc.w = acc.w * inv + bb.w;
            orow[cidx] = acc;
        }
    }
}

// ================= launch =================
extern "C" void kernel_launch(void* const* d_in, const int* in_sizes, int n_in,
                              void* d_out, int out_size)
{
    const float* x  = (const float*)d_in[0];
    const float* Wq = (const float*)d_in[1];
    const float* bq = (const float*)d_in[2];
    const float* Wk = (const float*)d_in[3];
    const float* Wv = (const float*)d_in[5];
    const float* bv = (const float*)d_in[6];
    const float* Wo = (const float*)d_in[7];
    const float* bo = (const float*)d_in[8];
    float* out = (float*)d_out;

    float *xp, *A, *Aq, *Ak, *bqA, *bvo, *WqT, *WvT, *WoT, *WcT, *L1, *L2, *xa, *AFo;
    cudaGetSymbolAddress((void**)&xp,  g_xp);
    cudaGetSymbolAddress((void**)&A,   g_A);
    cudaGetSymbolAddress((void**)&Aq,  g_Aq);
    cudaGetSymbolAddress((void**)&Ak,  g_Ak);
    cudaGetSymbolAddress((void**)&bqA, g_bqA);
    cudaGetSymbolAddress((void**)&bvo, g_bvo);
    cudaGetSymbolAddress((void**)&WqT, g_WqT);
    cudaGetSymbolAddress((void**)&WvT, g_WvT);
    cudaGetSymbolAddress((void**)&WoT, g_WoT);
    cudaGetSymbolAddress((void**)&WcT, g_WcT);
    cudaGetSymbolAddress((void**)&L1,  g_L1);
    cudaGetSymbolAddress((void**)&L2,  g_L2);
    cudaGetSymbolAddress((void**)&xa,  g_xa);
    cudaGetSymbolAddress((void**)&AFo, g_AFo);

    static int attr_set = 0;
    if (!attr_set) {
        cudaFuncSetAttribute(gemm_nn,         cudaFuncAttributeMaxDynamicSharedMemorySize, GEMM_SMEM);
        cudaFuncSetAttribute(logits12_kernel, cudaFuncAttributeMaxDynamicSharedMemorySize, L12_SMEM);
        cudaFuncSetAttribute(xa_kernel,       cudaFuncAttributeMaxDynamicSharedMemorySize, XA_SMEM);
        attr_set = 1;
    }

    // independent preprocessing
    transpose3<<<dim3(16, 16, 3), dim3(32, 8)>>>(Wq, Wv, Wo, WqT, WvT, WoT);
    pool_x_kernel<<<1024, 512>>>(x, xp);
    rowdot_kernel<<<64, 256>>>(Wo, bv, bvo);                        // bvo = Wo . bv
    gemm_nn<<<dim3(8, 8),  256, GEMM_SMEM>>>(WvT, WoT, WoT, nullptr, WcT, WcT, 8);  // WcT = WvT@WoT

    // main chain
    gemm_nn<<<dim3(8, 16), 256, GEMM_SMEM>>>(xp, WqT, WqT, bq, A, A, 8);            // A = xp@Wq^T + bq
    gemm_nn<<<dim3(16, 16), 256, GEMM_SMEM>>>(A, Wq, Wk, nullptr, Aq, Ak, 8);       // Aq, Ak
    rowdot_kernel<<<128, 256>>>(A, bq, bqA);                        // bqA = A . bq

    logits12_kernel<<<dim3(8, 64), 256, L12_SMEM>>>(Aq, Ak, bqA, x, L1, L2);
    xa_kernel<<<dim3(4, 64), 256, XA_SMEM>>>(L2, x, xa);
    gemm_nn<<<dim3(8, 16), 256, GEMM_SMEM>>>(xa, WcT, WcT, bvo, AFo, AFo, 8);       // AFo = xa@WcT + bvo
    final_kernel<<<dim3(16, 64), 512>>>(L1, AFo, bo, out);
}

// round 12
// speedup vs baseline: 2.8965x; 1.2265x over previous
#include <cuda_runtime.h>
#include <cuda_fp16.h>
#include <math.h>
#include <stdint.h>

#define Cn 512
#define Bn 64
#define Nn 1024
#define Mn 16
#define SCALE 0.04419417382415922f   // 512^-0.5

// ---------------- scratch (allocation-free) ----------------
__device__ float g_xp  [1024 * 512];
__device__ float g_A   [1024 * 512];
__device__ float g_Aq  [1024 * 512];
__device__ float g_Ak  [1024 * 512];
__device__ float g_bqA [1024];
__device__ float g_bvo [512];
__device__ float g_WqT [512 * 512];
__device__ float g_WvT [512 * 512];
__device__ float g_WoT [512 * 512];
__device__ float g_WcT [512 * 512];
__device__ float g_L2  [64 * 16 * 1024];
__device__ float g_L1  [64 * 1024 * 16];
__device__ float g_xa  [1024 * 512];
__device__ float g_AFo [1024 * 512];
__device__ __half g_xh  [(size_t)64 * 1024 * 512];
__device__ __half g_xl  [(size_t)64 * 1024 * 512];
__device__ __half g_aqkh[64 * 32 * 512];
__device__ __half g_aqkl[64 * 32 * 512];

__device__ __forceinline__ uint32_t smem_u32(const void* p) {
    return (uint32_t)__cvta_generic_to_shared(p);
}
__device__ __forceinline__ void cp_async16(uint32_t s, const void* g) {
    asm volatile("cp.async.cg.shared.global [%0], [%1], 16;" :: "r"(s), "l"(g));
}
__device__ __forceinline__ void ldx4(uint32_t* r, uint32_t addr) {
    asm volatile("ldmatrix.sync.aligned.m8n8.x4.shared.b16 {%0,%1,%2,%3}, [%4];"
                 : "=r"(r[0]), "=r"(r[1]), "=r"(r[2]), "=r"(r[3]) : "r"(addr));
}
__device__ __forceinline__ void ldx2t(uint32_t* r, uint32_t addr) {
    asm volatile("ldmatrix.sync.aligned.m8n8.x2.trans.shared.b16 {%0,%1}, [%2];"
                 : "=r"(r[0]), "=r"(r[1]) : "r"(addr));
}
__device__ __forceinline__ void mma16816(float* c, const uint32_t* a, uint32_t b0, uint32_t b1) {
    asm volatile(
        "mma.sync.aligned.m16n8k16.row.col.f32.f16.f16.f32 "
        "{%0,%1,%2,%3}, {%4,%5,%6,%7}, {%8,%9}, {%0,%1,%2,%3};"
        : "+f"(c[0]), "+f"(c[1]), "+f"(c[2]), "+f"(c[3])
        : "r"(a[0]), "r"(a[1]), "r"(a[2]), "r"(a[3]), "r"(b0), "r"(b1));
}

// ================= transpose3 (unchanged) =================
__global__ void transpose3(const float* __restrict__ Wq, const float* __restrict__ Wv,
                           const float* __restrict__ Wo, float* __restrict__ WqT,
                           float* __restrict__ WvT, float* __restrict__ WoT)
{
    __shared__ float t[32][33];
    const float* s; float* d;
    if (blockIdx.z == 0)      { s = Wq; d = WqT; }
    else if (blockIdx.z == 1) { s = Wv; d = WvT; }
    else                      { s = Wo; d = WoT; }
    const int x  = blockIdx.x * 32 + threadIdx.x;
    const int y0 = blockIdx.y * 32 + threadIdx.y;
#pragma unroll
    for (int j = 0; j < 32; j += 8)
        t[threadIdx.y + j][threadIdx.x] = s[(size_t)(y0 + j) * Cn + x];
    __syncthreads();
    const int ox  = blockIdx.y * 32 + threadIdx.x;
    const int oy0 = blockIdx.x * 32 + threadIdx.y;
#pragma unroll
    for (int j = 0; j < 32; j += 8)
        d[(size_t)(oy0 + j) * Cn + ox] = t[threadIdx.x][threadIdx.y + j];
}

// ================= split x -> fp16 hi/lo + pooled xp =================
__global__ __launch_bounds__(512)
void split_pool_kernel(const float* __restrict__ x, __half* __restrict__ xh,
                       __half* __restrict__ xl, float* __restrict__ xp)
{
    const int bm = blockIdx.x;
    const int c  = threadIdx.x;
    const size_t ob = (size_t)bm * 64 * Cn + c;
    const float* base = x + ob;
    float s = 0.f;
#pragma unroll 4
    for (int t = 0; t < 64; t++) {
        float v = base[(size_t)t * Cn];
        s += v;
        __half h = __float2half(v);
        xh[ob + (size_t)t * Cn] = h;
        xl[ob + (size_t)t * Cn] = __float2half(v - __half2float(h));
    }
    xp[(size_t)bm * Cn + c] = s * (1.0f / 64.0f);
}

// ================= convert Aq|Ak -> packed fp16 hi/lo [b][32][512] =================
__global__ void cvt_aqk(const float* __restrict__ Aq, const float* __restrict__ Ak,
                        __half* __restrict__ Ah, __half* __restrict__ Al)
{
    const int i = blockIdx.x * 256 + threadIdx.x;   // 64*32*512 = 1048576
    const int k = i & 511;
    const int j = (i >> 9) & 31;
    const int b = i >> 14;
    float v = (j < 16) ? Aq[((size_t)b * 16 + j) * Cn + k]
                       : Ak[((size_t)b * 16 + (j - 16)) * Cn + k];
    __half h = __float2half(v);
    Ah[i] = h;
    Al[i] = __float2half(v - __half2float(h));
}

// ================= NN GEMM (unchanged from R11) =================
#define XS_FLOATS (64 * 36)
#define WS_FLOATS (32 * 68)
#define STAGE_FLOATS (XS_FLOATS + WS_FLOATS)
#define GEMM_SMEM (3 * STAGE_FLOATS * 4)

__global__ __launch_bounds__(256)
void gemm_nn(const float* __restrict__ X, const float* __restrict__ W0,
             const float* __restrict__ W1, const float* __restrict__ bias,
             float* __restrict__ Y0, float* __restrict__ Y1, int nsplit)
{
    extern __shared__ float sm[];
    const int tid = threadIdx.x;
    const int tx = tid & 15, ty = tid >> 4;
    const int r0 = blockIdx.y * 64;
    const float* W; float* Y; int n0;
    if ((int)blockIdx.x < nsplit) { W = W0; Y = Y0; n0 = blockIdx.x * 64; }
    else                          { W = W1; Y = Y1; n0 = (blockIdx.x - nsplit) * 64; }

    const int xlr = tid >> 2, xlk = (tid & 3) * 8;
    const int wwk = tid >> 3, wwn = (tid & 7) * 8;
    const float* gX = X + (size_t)(r0 + xlr) * Cn + xlk;
    const float* gW = W + (size_t)wwk * Cn + n0 + wwn;
    const uint32_t sbase = smem_u32(sm);
    const uint32_t xdst = sbase + (uint32_t)(xlr * 36 + xlk) * 4u;
    const uint32_t wdst = sbase + (uint32_t)(XS_FLOATS + wwk * 68 + wwn) * 4u;

#define G_LOAD(ST, K0)                                                          \
    do {                                                                        \
        const uint32_t so_ = (uint32_t)(ST) * (STAGE_FLOATS * 4u);              \
        cp_async16(xdst + so_,      gX + (K0));                                 \
        cp_async16(xdst + so_ + 16, gX + (K0) + 4);                             \
        cp_async16(wdst + so_,      gW + (size_t)(K0) * Cn);                    \
        cp_async16(wdst + so_ + 16, gW + (size_t)(K0) * Cn + 4);                \
        asm volatile("cp.async.commit_group;" ::: "memory");                    \
    } while (0)

    float acc[4][4];
#pragma unroll
    for (int i = 0; i < 4; i++)
#pragma unroll
        for (int j = 0; j < 4; j++) acc[i][j] = 0.f;

    G_LOAD(0, 0);
    G_LOAD(1, 32);

#pragma unroll 1
    for (int it = 0; it < 16; it++) {
        if (it < 15) asm volatile("cp.async.wait_group 1;" ::: "memory");
        else         asm volatile("cp.async.wait_group 0;" ::: "memory");
        __syncthreads();
        if (it + 2 < 16) G_LOAD((it + 2) % 3, (it + 2) * 32);

        const float* Xst = sm + (it % 3) * STAGE_FLOATS;
        const float* Wst = Xst + XS_FLOATS;
#pragma unroll
        for (int k4 = 0; k4 < 8; k4++) {
            float aa[4][4], bb[4][4];
#pragma unroll
            for (int i = 0; i < 4; i++) {
                float4 a = *(const float4*)(Xst + (ty * 4 + i) * 36 + k4 * 4);
                aa[i][0] = a.x; aa[i][1] = a.y; aa[i][2] = a.z; aa[i][3] = a.w;
            }
#pragma unroll
            for (int q = 0; q < 4; q++) {
                float4 b = *(const float4*)(Wst + (k4 * 4 + q) * 68 + tx * 4);
                bb[q][0] = b.x; bb[q][1] = b.y; bb[q][2] = b.z; bb[q][3] = b.w;
            }
#pragma unroll
            for (int i = 0; i < 4; i++)
#pragma unroll
                for (int j = 0; j < 4; j++)
#pragma unroll
                    for (int q = 0; q < 4; q++)
                        acc[i][j] = fmaf(aa[i][q], bb[q][j], acc[i][j]);
        }
    }
#undef G_LOAD

    float4 bi = make_float4(0.f, 0.f, 0.f, 0.f);
    if (bias) bi = *(const float4*)(bias + n0 + tx * 4);
#pragma unroll
    for (int i = 0; i < 4; i++) {
        float4 o;
        o.x = acc[i][0] + bi.x; o.y = acc[i][1] + bi.y;
        o.z = acc[i][2] + bi.z; o.w = acc[i][3] + bi.w;
        *(float4*)(Y + (size_t)(r0 + ty * 4 + i) * Cn + n0 + tx * 4) = o;
    }
}

// ================= rowdot (unchanged) =================
__global__ void rowdot_kernel(const float* __restrict__ src, const float* __restrict__ vec,
                              float* __restrict__ dst)
{
    const int row  = blockIdx.x * 8 + (threadIdx.x >> 5);
    const int lane = threadIdx.x & 31;
    const float* sr = src + (size_t)row * Cn;
    float s = 0.f;
#pragma unroll
    for (int k = 0; k < 16; k++) s += sr[lane + 32 * k] * __ldg(&vec[lane + 32 * k]);
#pragma unroll
    for (int off = 16; off > 0; off >>= 1) s += __shfl_xor_sync(0xffffffffu, s, off);
    if (lane == 0) dst[row] = s;
}

// ================= logits via mma: L1[b,n,m], L2[b,m,n] =================
// block: 128 tokens (8 warps x m16), all 32 j (Aq|Ak), K=512 in 8 chunks of 64.
#define LG_STAGE 40960       // xh 16K + xl 16K + Ah 4K + Al 4K
#define LG_SMEM (2 * LG_STAGE + 64)

__global__ __launch_bounds__(256)
void logits12_mma(const __half* __restrict__ Xh, const __half* __restrict__ Xl,
                  const __half* __restrict__ Ah_g, const __half* __restrict__ Al_g,
                  const float* __restrict__ bqA,
                  float* __restrict__ L1, float* __restrict__ L2)
{
    extern __shared__ char smem[];
    const uint32_t sbase = smem_u32(smem);
    const int b = blockIdx.y;
    const int tokblk = blockIdx.x * 128;
    const int t = threadIdx.x;
    const int L = t & 31;
    const int w = t >> 5;

    if (t < 16) ((float*)(smem + 2 * LG_STAGE))[t] = bqA[b * 16 + t];

#define LG_LOAD(I)                                                                        \
    do {                                                                                  \
        const int s_ = (I) & 1; const int k0_ = (I) * 64;                                 \
        const uint32_t sb_ = sbase + s_ * LG_STAGE;                                       \
        {                                                                                 \
            const int row = t >> 1; const int cb = (t & 1) * 4;                           \
            const __half* gh = Xh + ((size_t)(b * Nn + tokblk + row)) * Cn + k0_ + cb * 8;\
            const __half* gl = Xl + ((size_t)(b * Nn + tokblk + row)) * Cn + k0_ + cb * 8;\
            _Pragma("unroll")                                                             \
            for (int j = 0; j < 4; j++) {                                                 \
                uint32_t o = (uint32_t)(row * 128 + (cb + j) * 16) ^ ((uint32_t)(row & 7) << 4); \
                cp_async16(sb_ + o, gh + j * 8);                                          \
                cp_async16(sb_ + 16384 + o, gl + j * 8);                                  \
            }                                                                             \
        }                                                                                 \
        {                                                                                 \
            const int jr = t >> 3; const int ch = t & 7;                                  \
            uint32_t o = (uint32_t)(jr * 128 + ch * 16) ^ ((uint32_t)(jr & 7) << 4);      \
            cp_async16(sb_ + 32768 + o, Ah_g + ((size_t)(b * 32 + jr)) * Cn + k0_ + ch * 8); \
            cp_async16(sb_ + 36864 + o, Al_g + ((size_t)(b * 32 + jr)) * Cn + k0_ + ch * 8); \
        }                                                                                 \
        asm volatile("cp.async.commit_group;" ::: "memory");                              \
    } while (0)

    float acc[4][4];
#pragma unroll
    for (int i = 0; i < 4; i++)
#pragma unroll
        for (int j = 0; j < 4; j++) acc[i][j] = 0.f;

    LG_LOAD(0);
    LG_LOAD(1);

    const int a_row = w * 16 + (L & 15);
    const int a_cx  = ((L >> 4) & 1) * 16;
    const int b_rb  = (L & 7) + ((L >> 4) & 1) * 8;
    const int b_cx  = ((L >> 3) & 1) * 16;

#pragma unroll 1
    for (int kt = 0; kt < 8; kt++) {
        if (kt < 7) asm volatile("cp.async.wait_group 1;" ::: "memory");
        else        asm volatile("cp.async.wait_group 0;" ::: "memory");
        __syncthreads();
        const uint32_t sb_ = sbase + (kt & 1) * LG_STAGE;
#pragma unroll
        for (int ks = 0; ks < 4; ks++) {
            uint32_t ah[4], al[4];
            uint32_t oa = (uint32_t)(a_row * 128 + ks * 32 + a_cx) ^ ((uint32_t)(a_row & 7) << 4);
            ldx4(ah, sb_ + oa);
            ldx4(al, sb_ + 16384 + oa);
            uint32_t bh[2][4], bl[2][4];
#pragma unroll
            for (int p = 0; p < 2; p++) {
                const int rn = b_rb + p * 16;
                uint32_t ob_ = (uint32_t)(rn * 128 + ks * 32 + b_cx) ^ ((uint32_t)(rn & 7) << 4);
                ldx4(bh[p], sb_ + 32768 + ob_);
                ldx4(bl[p], sb_ + 36864 + ob_);
            }
#pragma unroll
            for (int nt = 0; nt < 4; nt++) {
                const int p = nt >> 1, pi = (nt & 1) * 2;
                mma16816(acc[nt], ah, bh[p][pi], bh[p][pi + 1]);
                mma16816(acc[nt], ah, bl[p][pi], bl[p][pi + 1]);
                mma16816(acc[nt], al, bh[p][pi], bh[p][pi + 1]);
            }
        }
        if (kt + 2 < 8) { __syncthreads(); LG_LOAD(kt + 2); }
    }
#undef LG_LOAD

    const int g  = L >> 2;
    const int cq = (L & 3) * 2;
    const float* bqs = (const float*)(smem + 2 * LG_STAGE);
    const int tk0 = tokblk + w * 16 + g;
#pragma unroll
    for (int nt = 0; nt < 4; nt++) {
        const int j0 = nt * 8 + cq;
        if (nt < 2) {
            float2 v0 = make_float2((acc[nt][0] + bqs[j0]) * SCALE, (acc[nt][1] + bqs[j0 + 1]) * SCALE);
            float2 v1 = make_float2((acc[nt][2] + bqs[j0]) * SCALE, (acc[nt][3] + bqs[j0 + 1]) * SCALE);
            *(float2*)(L1 + ((size_t)b * Nn + tk0)     * 16 + j0) = v0;
            *(float2*)(L1 + ((size_t)b * Nn + tk0 + 8) * 16 + j0) = v1;
        } else {
            const int m0 = j0 - 16;
            L2[((size_t)b * 16 + m0)     * Nn + tk0]     = acc[nt][0] * SCALE;
            L2[((size_t)b * 16 + m0 + 1) * Nn + tk0]     = acc[nt][1] * SCALE;
            L2[((size_t)b * 16 + m0)     * Nn + tk0 + 8] = acc[nt][2] * SCALE;
            L2[((size_t)b * 16 + m0 + 1) * Nn + tk0 + 8] = acc[nt][3] * SCALE;
        }
    }
}

// ================= xa via mma: xa[b,m,c] = softmax_n(L2[b,m,:]) @ x[b] =================
// block: 64 channels (8 warps x n8), m16, K=1024 tokens in 16 chunks of 64.
#define PS_STRIDE 1040
#define XA_PS 33280              // bytes of one ps array (16*1040*2)
#define XA_XOFF 66560
#define XA_STAGE 16384           // xh 8K + xl 8K
#define XA_SMEM (XA_XOFF + 2 * XA_STAGE)   // 99328

__global__ __launch_bounds__(256)
void xa_mma(const float* __restrict__ L2, const __half* __restrict__ Xh,
            const __half* __restrict__ Xl, float* __restrict__ xa)
{
    extern __shared__ char smem[];
    const uint32_t sbase = smem_u32(smem);
    const int b  = blockIdx.y;
    const int c0 = blockIdx.x * 64;
    const int t  = threadIdx.x;
    const int L  = t & 31;
    const int w  = t >> 5;

    // phase A: softmax rows -> fp16 hi/lo in smem
    __half* psh = (__half*)smem;
    __half* psl = (__half*)(smem + XA_PS);
    for (int mr = w; mr < 16; mr += 8) {
        const float* row = L2 + ((size_t)b * 16 + mr) * Nn;
        float mx = -INFINITY;
#pragma unroll
        for (int i = 0; i < 32; i++) mx = fmaxf(mx, __ldg(row + L + 32 * i));
#pragma unroll
        for (int off = 16; off > 0; off >>= 1)
            mx = fmaxf(mx, __shfl_xor_sync(0xffffffffu, mx, off));
        float sum = 0.f;
#pragma unroll
        for (int i = 0; i < 32; i++) sum += __expf(__ldg(row + L + 32 * i) - mx);
#pragma unroll
        for (int off = 16; off > 0; off >>= 1)
            sum += __shfl_xor_sync(0xffffffffu, sum, off);
        const float inv = 1.0f / sum;
#pragma unroll
        for (int i = 0; i < 32; i++) {
            float e = __expf(__ldg(row + L + 32 * i) - mx) * inv;
            __half h = __float2half(e);
            psh[mr * PS_STRIDE + L + 32 * i] = h;
            psl[mr * PS_STRIDE + L + 32 * i] = __float2half(e - __half2float(h));
        }
    }
    __syncthreads();

#define XA_LOAD(I)                                                                        \
    do {                                                                                  \
        const int s_ = (I) & 1; const int k0_ = (I) * 64;                                 \
        const uint32_t xb_ = sbase + XA_XOFF + s_ * XA_STAGE;                             \
        const int row = t >> 2; const int cb = (t & 3) * 2;                               \
        const __half* gh = Xh + ((size_t)(b * Nn + k0_ + row)) * Cn + c0 + cb * 8;        \
        const __half* gl = Xl + ((size_t)(b * Nn + k0_ + row)) * Cn + c0 + cb * 8;        \
        _Pragma("unroll")                                                                 \
        for (int j = 0; j < 2; j++) {                                                     \
            uint32_t o = (uint32_t)(row * 128 + (cb + j) * 16) ^ ((uint32_t)(row & 7) << 4); \
            cp_async16(xb_ + o, gh + j * 8);                                              \
            cp_async16(xb_ + 8192 + o, gl + j * 8);                                       \
        }                                                                                 \
        asm volatile("cp.async.commit_group;" ::: "memory");                              \
    } while (0)

    float acc[4] = {0.f, 0.f, 0.f, 0.f};
    XA_LOAD(0);
    XA_LOAD(1);

    const int arow = L & 15;
    const int asel = ((L >> 4) & 1) * 16;
    const int brl  = L & 15;
    const uint32_t ph_b = sbase;
    const uint32_t pl_b = sbase + XA_PS;

#pragma unroll 1
    for (int kt = 0; kt < 16; kt++) {
        if (kt < 15) asm volatile("cp.async.wait_group 1;" ::: "memory");
        else         asm volatile("cp.async.wait_group 0;" ::: "memory");
        __syncthreads();
        const uint32_t xb_ = sbase + XA_XOFF + (kt & 1) * XA_STAGE;
#pragma unroll
        for (int ks = 0; ks < 4; ks++) {
            const int kbyte = (kt * 64 + ks * 16) * 2 + asel;
            uint32_t pa[4], pb2[4];
            ldx4(pa,  ph_b + (uint32_t)(arow * (PS_STRIDE * 2) + kbyte));
            ldx4(pb2, pl_b + (uint32_t)(arow * (PS_STRIDE * 2) + kbyte));
            const int r = ks * 16 + brl;
            uint32_t ob_ = (uint32_t)(r * 128 + w * 16) ^ ((uint32_t)(r & 7) << 4);
            uint32_t bh[2], bl2[2];
            ldx2t(bh,  xb_ + ob_);
            ldx2t(bl2, xb_ + 8192 + ob_);
            mma16816(acc, pa,  bh[0],  bh[1]);
            mma16816(acc, pa,  bl2[0], bl2[1]);
            mma16816(acc, pb2, bh[0],  bh[1]);
        }
        if (kt + 2 < 16) { __syncthreads(); XA_LOAD(kt + 2); }
    }
#undef XA_LOAD

    const int g  = L >> 2;
    const int cq = (L & 3) * 2;
    const int c  = c0 + w * 8 + cq;
    *(float2*)(xa + ((size_t)b * 16 + g)     * Cn + c) = make_float2(acc[0], acc[1]);
    *(float2*)(xa + ((size_t)b * 16 + g + 8) * Cn + c) = make_float2(acc[2], acc[3]);
}

// ================= final (unchanged from R11) =================
__global__ __launch_bounds__(512)
void final_kernel(const float* __restrict__ L1, const float* __restrict__ AFo,
                  const float* __restrict__ bo, float* __restrict__ out)
{
    __shared__ float4 afo4[Mn * 128];
    __shared__ float  l1s[64 * 16];
    __shared__ float4 bo4[128];
    const int b    = blockIdx.y;
    const int n0   = blockIdx.x * 64;
    const int tid  = threadIdx.x;
    const int warp = tid >> 5;
    const int lane = tid & 31;

    {
        const float4* s = (const float4*)(AFo + (size_t)b * Mn * Cn);
        for (int i = tid; i < 2048; i += 512) afo4[i] = s[i];
        const float4* sl = (const float4*)(L1 + ((size_t)b * Nn + n0) * 16);
        if (tid < 256) ((float4*)l1s)[tid] = sl[tid];
        if (tid < 128) bo4[tid] = ((const float4*)bo)[tid];
    }
    __syncthreads();

#pragma unroll 1
    for (int t = 0; t < 4; t++) {
        const int tok = warp * 4 + t;
        float lg[16];
#pragma unroll
        for (int m = 0; m < Mn; m++) lg[m] = l1s[tok * 16 + m];
        float mx = lg[0];
#pragma unroll
        for (int m = 1; m < Mn; m++) mx = fmaxf(mx, lg[m]);
        float s = 0.f;
#pragma unroll
        for (int m = 0; m < Mn; m++) { lg[m] = __expf(lg[m] - mx); s += lg[m]; }
        const float inv = 1.0f / s;

        float4* orow = (float4*)(out + ((size_t)b * Nn + n0 + tok) * Cn);
#pragma unroll 1
        for (int kc = 0; kc < 4; kc++) {
            const int cidx = kc * 32 + lane;
            float4 acc = make_float4(0.f, 0.f, 0.f, 0.f);
#pragma unroll
            for (int m = 0; m < Mn; m++) {
                float4 f = afo4[m * 128 + cidx];
                acc.x = fmaf(lg[m], f.x, acc.x);
                acc.y = fmaf(lg[m], f.y, acc.y);
                acc.z = fmaf(lg[m], f.z, acc.z);
                acc.w = fmaf(lg[m], f.w, acc.w);
            }
            float4 bb = bo4[cidx];
            acc.x = acc.x * inv + bb.x;
            acc.y = acc.y * inv + bb.y;
            acc.z = acc.z * inv + bb.z;
            acc.w = acc.w * inv + bb.w;
            orow[cidx] = acc;
        }
    }
}

// ================= launch =================
extern "C" void kernel_launch(void* const* d_in, const int* in_sizes, int n_in,
                              void* d_out, int out_size)
{
    const float* x  = (const float*)d_in[0];
    const float* Wq = (const float*)d_in[1];
    const float* bq = (const float*)d_in[2];
    const float* Wk = (const float*)d_in[3];
    const float* Wv = (const float*)d_in[5];
    const float* bv = (const float*)d_in[6];
    const float* Wo = (const float*)d_in[7];
    const float* bo = (const float*)d_in[8];
    float* out = (float*)d_out;

    float *xp, *A, *Aq, *Ak, *bqA, *bvo, *WqT, *WvT, *WoT, *WcT, *L1, *L2, *xa, *AFo;
    __half *xh, *xl, *aqkh, *aqkl;
    cudaGetSymbolAddress((void**)&xp,   g_xp);
    cudaGetSymbolAddress((void**)&A,    g_A);
    cudaGetSymbolAddress((void**)&Aq,   g_Aq);
    cudaGetSymbolAddress((void**)&Ak,   g_Ak);
    cudaGetSymbolAddress((void**)&bqA,  g_bqA);
    cudaGetSymbolAddress((void**)&bvo,  g_bvo);
    cudaGetSymbolAddress((void**)&WqT,  g_WqT);
    cudaGetSymbolAddress((void**)&WvT,  g_WvT);
    cudaGetSymbolAddress((void**)&WoT,  g_WoT);
    cudaGetSymbolAddress((void**)&WcT,  g_WcT);
    cudaGetSymbolAddress((void**)&L1,   g_L1);
    cudaGetSymbolAddress((void**)&L2,   g_L2);
    cudaGetSymbolAddress((void**)&xa,   g_xa);
    cudaGetSymbolAddress((void**)&AFo,  g_AFo);
    cudaGetSymbolAddress((void**)&xh,   g_xh);
    cudaGetSymbolAddress((void**)&xl,   g_xl);
    cudaGetSymbolAddress((void**)&aqkh, g_aqkh);
    cudaGetSymbolAddress((void**)&aqkl, g_aqkl);

    static int attr_set = 0;
    if (!attr_set) {
        cudaFuncSetAttribute(gemm_nn,      cudaFuncAttributeMaxDynamicSharedMemorySize, GEMM_SMEM);
        cudaFuncSetAttribute(logits12_mma, cudaFuncAttributeMaxDynamicSharedMemorySize, LG_SMEM);
        cudaFuncSetAttribute(xa_mma,       cudaFuncAttributeMaxDynamicSharedMemorySize, XA_SMEM);
        attr_set = 1;
    }

    // preprocessing
    transpose3<<<dim3(16, 16, 3), dim3(32, 8)>>>(Wq, Wv, Wo, WqT, WvT, WoT);
    split_pool_kernel<<<1024, 512>>>(x, xh, xl, xp);
    rowdot_kernel<<<64, 256>>>(Wo, bv, bvo);
    gemm_nn<<<dim3(8, 8),  256, GEMM_SMEM>>>(WvT, WoT, WoT, nullptr, WcT, WcT, 8);

    // main chain
    gemm_nn<<<dim3(8, 16), 256, GEMM_SMEM>>>(xp, WqT, WqT, bq, A, A, 8);
    gemm_nn<<<dim3(16, 16), 256, GEMM_SMEM>>>(A, Wq, Wk, nullptr, Aq, Ak, 8);
    rowdot_kernel<<<128, 256>>>(A, bq, bqA);
    cvt_aqk<<<4096, 256>>>(Aq, Ak, aqkh, aqkl);

    logits12_mma<<<dim3(8, 64), 256, LG_SMEM>>>(xh, xl, aqkh, aqkl, bqA, L1, L2);
    xa_mma<<<dim3(8, 64), 256, XA_SMEM>>>(L2, xh, xl, xa);
    gemm_nn<<<dim3(8, 16), 256, GEMM_SMEM>>>(xa, WcT, WcT, bvo, AFo, AFo, 8);
    final_kernel<<<dim3(16, 64), 512>>>(L1, AFo, bo, out);
}

// round 13
// speedup vs baseline: 3.0421x; 1.0503x over previous
#include <cuda_runtime.h>
#include <cuda_fp16.h>
#include <math.h>
#include <stdint.h>

#define Cn 512
#define Bn 64
#define Nn 1024
#define Mn 16
#define SCALE 0.04419417382415922f   // 512^-0.5

// ---------------- scratch (allocation-free) ----------------
__device__ float g_xp  [1024 * 512];
__device__ float g_A   [1024 * 512];
__device__ float g_bqA [1024];
__device__ float g_bvo [512];
__device__ float g_WqT [512 * 512];
__device__ float g_WvT [512 * 512];
__device__ float g_WoT [512 * 512];
__device__ float g_WcT [512 * 512];
__device__ float g_L2  [64 * 16 * 1024];
__device__ float g_L1  [64 * 1024 * 16];
__device__ float g_xa  [1024 * 512];
__device__ float g_AFo [1024 * 512];
__device__ __half g_xh  [(size_t)64 * 1024 * 512];
__device__ __half g_xl  [(size_t)64 * 1024 * 512];
__device__ __half g_aqkh[64 * 32 * 512];
__device__ __half g_aqkl[64 * 32 * 512];

__device__ __forceinline__ uint32_t smem_u32(const void* p) {
    return (uint32_t)__cvta_generic_to_shared(p);
}
__device__ __forceinline__ void cp_async16(uint32_t s, const void* g) {
    asm volatile("cp.async.cg.shared.global [%0], [%1], 16;" :: "r"(s), "l"(g));
}
__device__ __forceinline__ void ldx4(uint32_t* r, uint32_t addr) {
    asm volatile("ldmatrix.sync.aligned.m8n8.x4.shared.b16 {%0,%1,%2,%3}, [%4];"
                 : "=r"(r[0]), "=r"(r[1]), "=r"(r[2]), "=r"(r[3]) : "r"(addr));
}
__device__ __forceinline__ void ldx2t(uint32_t* r, uint32_t addr) {
    asm volatile("ldmatrix.sync.aligned.m8n8.x2.trans.shared.b16 {%0,%1}, [%2];"
                 : "=r"(r[0]), "=r"(r[1]) : "r"(addr));
}
__device__ __forceinline__ void mma16816(float* c, const uint32_t* a, uint32_t b0, uint32_t b1) {
    asm volatile(
        "mma.sync.aligned.m16n8k16.row.col.f32.f16.f16.f32 "
        "{%0,%1,%2,%3}, {%4,%5,%6,%7}, {%8,%9}, {%0,%1,%2,%3};"
        : "+f"(c[0]), "+f"(c[1]), "+f"(c[2]), "+f"(c[3])
        : "r"(a[0]), "r"(a[1]), "r"(a[2]), "r"(a[3]), "r"(b0), "r"(b1));
}

// ================= prep: 3 transposes + bvo, one launch =================
__global__ void prep_kernel(const float* __restrict__ Wq, const float* __restrict__ Wv,
                            const float* __restrict__ Wo, const float* __restrict__ bv,
                            float* __restrict__ WqT, float* __restrict__ WvT,
                            float* __restrict__ WoT, float* __restrict__ bvo)
{
    if (blockIdx.z < 3) {
        __shared__ float t[32][33];
        const float* s; float* d;
        if (blockIdx.z == 0)      { s = Wq; d = WqT; }
        else if (blockIdx.z == 1) { s = Wv; d = WvT; }
        else                      { s = Wo; d = WoT; }
        const int x  = blockIdx.x * 32 + threadIdx.x;
        const int y0 = blockIdx.y * 32 + threadIdx.y;
#pragma unroll
        for (int j = 0; j < 32; j += 8)
            t[threadIdx.y + j][threadIdx.x] = s[(size_t)(y0 + j) * Cn + x];
        __syncthreads();
        const int ox  = blockIdx.y * 32 + threadIdx.x;
        const int oy0 = blockIdx.x * 32 + threadIdx.y;
#pragma unroll
        for (int j = 0; j < 32; j += 8)
            d[(size_t)(oy0 + j) * Cn + ox] = t[threadIdx.x][threadIdx.y + j];
        return;
    }
    // z == 3: bvo[r] = Wo[r,:] . bv  (one warp per row, 64 blocks x 8 warps)
    const int id  = blockIdx.y * 16 + blockIdx.x;
    const int tid = threadIdx.y * 32 + threadIdx.x;
    if (id < 64) {
        const int row  = id * 8 + (tid >> 5);
        const int lane = tid & 31;
        const float* sr = Wo + (size_t)row * Cn;
        float s = 0.f;
#pragma unroll
        for (int k = 0; k < 16; k++) s += sr[lane + 32 * k] * __ldg(&bv[lane + 32 * k]);
#pragma unroll
        for (int off = 16; off > 0; off >>= 1) s += __shfl_xor_sync(0xffffffffu, s, off);
        if (lane == 0) bvo[row] = s;
    }
}

// ================= split x -> fp16 hi/lo + pooled xp =================
__global__ __launch_bounds__(512)
void split_pool_kernel(const float* __restrict__ x, __half* __restrict__ xh,
                       __half* __restrict__ xl, float* __restrict__ xp)
{
    const int bm = blockIdx.x;
    const int c  = threadIdx.x;
    const size_t ob = (size_t)bm * 64 * Cn + c;
    const float* base = x + ob;
    float s = 0.f;
#pragma unroll 4
    for (int t = 0; t < 64; t++) {
        float v = base[(size_t)t * Cn];
        s += v;
        __half h = __float2half(v);
        xh[ob + (size_t)t * Cn] = h;
        xl[ob + (size_t)t * Cn] = __float2half(v - __half2float(h));
    }
    xp[(size_t)bm * Cn + c] = s * (1.0f / 64.0f);
}

// ================= GEMM smem config (shared by all gemm variants) =================
#define XS_FLOATS (64 * 36)
#define WS_FLOATS (32 * 68)
#define STAGE_FLOATS (XS_FLOATS + WS_FLOATS)
#define GEMM_SMEM (3 * STAGE_FLOATS * 4)

#define GEMM_PROLOGUE(Xp, Wp, R0, N0)                                           \
    const int tid = threadIdx.x;                                                \
    const int tx = tid & 15, ty = tid >> 4;                                     \
    const int xlr = tid >> 2, xlk = (tid & 3) * 8;                              \
    const int wwk = tid >> 3, wwn = (tid & 7) * 8;                              \
    const float* gX = (Xp) + (size_t)((R0) + xlr) * Cn + xlk;                   \
    const float* gW = (Wp) + (size_t)wwk * Cn + (N0) + wwn;                     \
    const uint32_t sbase = smem_u32(sm);                                        \
    const uint32_t xdst = sbase + (uint32_t)(xlr * 36 + xlk) * 4u;              \
    const uint32_t wdst = sbase + (uint32_t)(XS_FLOATS + wwk * 68 + wwn) * 4u;

#define G_LOAD(ST, K0)                                                          \
    do {                                                                        \
        const uint32_t so_ = (uint32_t)(ST) * (STAGE_FLOATS * 4u);              \
        cp_async16(xdst + so_,      gX + (K0));                                 \
        cp_async16(xdst + so_ + 16, gX + (K0) + 4);                             \
        cp_async16(wdst + so_,      gW + (size_t)(K0) * Cn);                    \
        cp_async16(wdst + so_ + 16, gW + (size_t)(K0) * Cn + 4);                \
        asm volatile("cp.async.commit_group;" ::: "memory");                    \
    } while (0)

#define GEMM_MAINLOOP(acc)                                                      \
    G_LOAD(0, 0);                                                               \
    G_LOAD(1, 32);                                                              \
    _Pragma("unroll 1")                                                         \
    for (int it = 0; it < 16; it++) {                                           \
        if (it < 15) asm volatile("cp.async.wait_group 1;" ::: "memory");       \
        else         asm volatile("cp.async.wait_group 0;" ::: "memory");       \
        __syncthreads();                                                        \
        if (it + 2 < 16) G_LOAD((it + 2) % 3, (it + 2) * 32);                   \
        const float* Xst = sm + (it % 3) * STAGE_FLOATS;                        \
        const float* Wst = Xst + XS_FLOATS;                                     \
        _Pragma("unroll")                                                       \
        for (int k4 = 0; k4 < 8; k4++) {                                        \
            float aa[4][4], bb[4][4];                                           \
            _Pragma("unroll")                                                   \
            for (int i = 0; i < 4; i++) {                                       \
                float4 a = *(const float4*)(Xst + (ty * 4 + i) * 36 + k4 * 4);  \
                aa[i][0] = a.x; aa[i][1] = a.y; aa[i][2] = a.z; aa[i][3] = a.w; \
            }                                                                   \
            _Pragma("unroll")                                                   \
            for (int q = 0; q < 4; q++) {                                       \
                float4 b = *(const float4*)(Wst + (k4 * 4 + q) * 68 + tx * 4);  \
                bb[q][0] = b.x; bb[q][1] = b.y; bb[q][2] = b.z; bb[q][3] = b.w; \
            }                                                                   \
            _Pragma("unroll")                                                   \
            for (int i = 0; i < 4; i++)                                         \
                _Pragma("unroll")                                               \
                for (int j = 0; j < 4; j++)                                     \
                    _Pragma("unroll")                                           \
                    for (int q = 0; q < 4; q++)                                 \
                        acc[i][j] = fmaf(aa[i][q], bb[q][j], acc[i][j]);        \
        }                                                                       \
    }

// ================= gemm_nn (fp32 out, single problem w/ dual-W split; used for AFo) =================
__global__ __launch_bounds__(256)
void gemm_nn(const float* __restrict__ X, const float* __restrict__ W0,
             const float* __restrict__ W1, const float* __restrict__ bias,
             float* __restrict__ Y0, float* __restrict__ Y1, int nsplit)
{
    extern __shared__ float sm[];
    const float* W; float* Y; int n0;
    if ((int)blockIdx.x < nsplit) { W = W0; Y = Y0; n0 = blockIdx.x * 64; }
    else                          { W = W1; Y = Y1; n0 = (blockIdx.x - nsplit) * 64; }
    const int r0 = blockIdx.y * 64;
    GEMM_PROLOGUE(X, W, r0, n0);

    float acc[4][4];
#pragma unroll
    for (int i = 0; i < 4; i++)
#pragma unroll
        for (int j = 0; j < 4; j++) acc[i][j] = 0.f;

    GEMM_MAINLOOP(acc);

    float4 bi = make_float4(0.f, 0.f, 0.f, 0.f);
    if (bias) bi = *(const float4*)(bias + n0 + tx * 4);
#pragma unroll
    for (int i = 0; i < 4; i++) {
        float4 o;
        o.x = acc[i][0] + bi.x; o.y = acc[i][1] + bi.y;
        o.z = acc[i][2] + bi.z; o.w = acc[i][3] + bi.w;
        *(float4*)(Y + (size_t)(r0 + ty * 4 + i) * Cn + n0 + tx * 4) = o;
    }
}

// ================= gemm_awc: merged A = xp@WqT + bq (128 blk) and WcT = WvT@WoT (64 blk) =================
__global__ __launch_bounds__(256)
void gemm_awc(const float* __restrict__ xp, const float* __restrict__ WqT,
              const float* __restrict__ bq, float* __restrict__ A,
              const float* __restrict__ WvT, const float* __restrict__ WoT,
              float* __restrict__ WcT)
{
    extern __shared__ float sm[];
    const float *X, *W, *bias; float* Y; int r0, n0;
    if ((int)blockIdx.x < 128) {
        const int l = blockIdx.x;
        X = xp; W = WqT; bias = bq; Y = A;
        n0 = (l & 7) * 64; r0 = (l >> 3) * 64;
    } else {
        const int l = blockIdx.x - 128;
        X = WvT; W = WoT; bias = nullptr; Y = WcT;
        n0 = (l & 7) * 64; r0 = (l >> 3) * 64;
    }
    GEMM_PROLOGUE(X, W, r0, n0);

    float acc[4][4];
#pragma unroll
    for (int i = 0; i < 4; i++)
#pragma unroll
        for (int j = 0; j < 4; j++) acc[i][j] = 0.f;

    GEMM_MAINLOOP(acc);

    float4 bi = make_float4(0.f, 0.f, 0.f, 0.f);
    if (bias) bi = *(const float4*)(bias + n0 + tx * 4);
#pragma unroll
    for (int i = 0; i < 4; i++) {
        float4 o;
        o.x = acc[i][0] + bi.x; o.y = acc[i][1] + bi.y;
        o.z = acc[i][2] + bi.z; o.w = acc[i][3] + bi.w;
        *(float4*)(Y + (size_t)(r0 + ty * 4 + i) * Cn + n0 + tx * 4) = o;
    }
}

// ================= gemm_aqk_h: Aq|Ak -> fp16 hi/lo packed [b][32][512] directly =================
// grid (16, 16): bx<8 -> Wq (j = m), bx>=8 -> Wk (j = m+16). n0 = (bx&7)*64.
__global__ __launch_bounds__(256)
void gemm_aqk_h(const float* __restrict__ A, const float* __restrict__ Wq,
                const float* __restrict__ Wk, __half* __restrict__ Ah,
                __half* __restrict__ Al)
{
    extern __shared__ float sm[];
    const int isK = (int)blockIdx.x >= 8;
    const float* W = isK ? Wk : Wq;
    const int n0 = ((int)blockIdx.x & 7) * 64;
    const int r0 = blockIdx.y * 64;
    GEMM_PROLOGUE(A, W, r0, n0);

    float acc[4][4];
#pragma unroll
    for (int i = 0; i < 4; i++)
#pragma unroll
        for (int j = 0; j < 4; j++) acc[i][j] = 0.f;

    GEMM_MAINLOOP(acc);

    const int joff = isK ? 16 : 0;
#pragma unroll
    for (int i = 0; i < 4; i++) {
        const int r = r0 + ty * 4 + i;          // row of [1024, 512]
        const int bb = r >> 4;
        const int j  = (r & 15) + joff;
        const size_t dst = ((size_t)bb * 32 + j) * Cn + n0 + tx * 4;
        __half h0 = __float2half(acc[i][0]);
        __half h1 = __float2half(acc[i][1]);
        __half h2 = __float2half(acc[i][2]);
        __half h3 = __float2half(acc[i][3]);
        *(__half2*)(Ah + dst)     = __halves2half2(h0, h1);
        *(__half2*)(Ah + dst + 2) = __halves2half2(h2, h3);
        *(__half2*)(Al + dst)     = __halves2half2(__float2half(acc[i][0] - __half2float(h0)),
                                                   __float2half(acc[i][1] - __half2float(h1)));
        *(__half2*)(Al + dst + 2) = __halves2half2(__float2half(acc[i][2] - __half2float(h2)),
                                                   __float2half(acc[i][3] - __half2float(h3)));
    }
}

// ================= rowdot: bqA[r] = A[r,:] . bq =================
__global__ void rowdot_kernel(const float* __restrict__ src, const float* __restrict__ vec,
                              float* __restrict__ dst)
{
    const int row  = blockIdx.x * 8 + (threadIdx.x >> 5);
    const int lane = threadIdx.x & 31;
    const float* sr = src + (size_t)row * Cn;
    float s = 0.f;
#pragma unroll
    for (int k = 0; k < 16; k++) s += sr[lane + 32 * k] * __ldg(&vec[lane + 32 * k]);
#pragma unroll
    for (int off = 16; off > 0; off >>= 1) s += __shfl_xor_sync(0xffffffffu, s, off);
    if (lane == 0) dst[row] = s;
}

// ================= logits via mma (unchanged from R12) =================
#define LG_STAGE 40960
#define LG_SMEM (2 * LG_STAGE + 64)

__global__ __launch_bounds__(256)
void logits12_mma(const __half* __restrict__ Xh, const __half* __restrict__ Xl,
                  const __half* __restrict__ Ah_g, const __half* __restrict__ Al_g,
                  const float* __restrict__ bqA,
                  float* __restrict__ L1, float* __restrict__ L2)
{
    extern __shared__ char smem[];
    const uint32_t sbase = smem_u32(smem);
    const int b = blockIdx.y;
    const int tokblk = blockIdx.x * 128;
    const int t = threadIdx.x;
    const int L = t & 31;
    const int w = t >> 5;

    if (t < 16) ((float*)(smem + 2 * LG_STAGE))[t] = bqA[b * 16 + t];

#define LG_LOAD(I)                                                                        \
    do {                                                                                  \
        const int s_ = (I) & 1; const int k0_ = (I) * 64;                                 \
        const uint32_t sb_ = sbase + s_ * LG_STAGE;                                       \
        {                                                                                 \
            const int row = t >> 1; const int cb = (t & 1) * 4;                           \
            const __half* gh = Xh + ((size_t)(b * Nn + tokblk + row)) * Cn + k0_ + cb * 8;\
            const __half* gl = Xl + ((size_t)(b * Nn + tokblk + row)) * Cn + k0_ + cb * 8;\
            _Pragma("unroll")                                                             \
            for (int j = 0; j < 4; j++) {                                                 \
                uint32_t o = (uint32_t)(row * 128 + (cb + j) * 16) ^ ((uint32_t)(row & 7) << 4); \
                cp_async16(sb_ + o, gh + j * 8);                                          \
                cp_async16(sb_ + 16384 + o, gl + j * 8);                                  \
            }                                                                             \
        }                                                                                 \
        {                                                                                 \
            const int jr = t >> 3; const int ch = t & 7;                                  \
            uint32_t o = (uint32_t)(jr * 128 + ch * 16) ^ ((uint32_t)(jr & 7) << 4);      \
            cp_async16(sb_ + 32768 + o, Ah_g + ((size_t)(b * 32 + jr)) * Cn + k0_ + ch * 8); \
            cp_async16(sb_ + 36864 + o, Al_g + ((size_t)(b * 32 + jr)) * Cn + k0_ + ch * 8); \
        }                                                                                 \
        asm volatile("cp.async.commit_group;" ::: "memory");                              \
    } while (0)

    float acc[4][4];
#pragma unroll
    for (int i = 0; i < 4; i++)
#pragma unroll
        for (int j = 0; j < 4; j++) acc[i][j] = 0.f;

    LG_LOAD(0);
    LG_LOAD(1);

    const int a_row = w * 16 + (L & 15);
    const int a_cx  = ((L >> 4) & 1) * 16;
    const int b_rb  = (L & 7) + ((L >> 4) & 1) * 8;
    const int b_cx  = ((L >> 3) & 1) * 16;

#pragma unroll 1
    for (int kt = 0; kt < 8; kt++) {
        if (kt < 7) asm volatile("cp.async.wait_group 1;" ::: "memory");
        else        asm volatile("cp.async.wait_group 0;" ::: "memory");
        __syncthreads();
        const uint32_t sb_ = sbase + (kt & 1) * LG_STAGE;
#pragma unroll
        for (int ks = 0; ks < 4; ks++) {
            uint32_t ah[4], al[4];
            uint32_t oa = (uint32_t)(a_row * 128 + ks * 32 + a_cx) ^ ((uint32_t)(a_row & 7) << 4);
            ldx4(ah, sb_ + oa);
            ldx4(al, sb_ + 16384 + oa);
            uint32_t bh[2][4], bl[2][4];
#pragma unroll
            for (int p = 0; p < 2; p++) {
                const int rn = b_rb + p * 16;
                uint32_t ob_ = (uint32_t)(rn * 128 + ks * 32 + b_cx) ^ ((uint32_t)(rn & 7) << 4);
                ldx4(bh[p], sb_ + 32768 + ob_);
                ldx4(bl[p], sb_ + 36864 + ob_);
            }
#pragma unroll
            for (int nt = 0; nt < 4; nt++) {
                const int p = nt >> 1, pi = (nt & 1) * 2;
                mma16816(acc[nt], ah, bh[p][pi], bh[p][pi + 1]);
                mma16816(acc[nt], ah, bl[p][pi], bl[p][pi + 1]);
                mma16816(acc[nt], al, bh[p][pi], bh[p][pi + 1]);
            }
        }
        if (kt + 2 < 8) { __syncthreads(); LG_LOAD(kt + 2); }
    }
#undef LG_LOAD

    const int g  = L >> 2;
    const int cq = (L & 3) * 2;
    const float* bqs = (const float*)(smem + 2 * LG_STAGE);
    const int tk0 = tokblk + w * 16 + g;
#pragma unroll
    for (int nt = 0; nt < 4; nt++) {
        const int j0 = nt * 8 + cq;
        if (nt < 2) {
            float2 v0 = make_float2((acc[nt][0] + bqs[j0]) * SCALE, (acc[nt][1] + bqs[j0 + 1]) * SCALE);
            float2 v1 = make_float2((acc[nt][2] + bqs[j0]) * SCALE, (acc[nt][3] + bqs[j0 + 1]) * SCALE);
            *(float2*)(L1 + ((size_t)b * Nn + tk0)     * 16 + j0) = v0;
            *(float2*)(L1 + ((size_t)b * Nn + tk0 + 8) * 16 + j0) = v1;
        } else {
            const int m0 = j0 - 16;
            L2[((size_t)b * 16 + m0)     * Nn + tk0]     = acc[nt][0] * SCALE;
            L2[((size_t)b * 16 + m0 + 1) * Nn + tk0]     = acc[nt][1] * SCALE;
            L2[((size_t)b * 16 + m0)     * Nn + tk0 + 8] = acc[nt][2] * SCALE;
            L2[((size_t)b * 16 + m0 + 1) * Nn + tk0 + 8] = acc[nt][3] * SCALE;
        }
    }
}

// ================= xa via mma (unchanged from R12) =================
#define PS_STRIDE 1040
#define XA_PS 33280
#define XA_XOFF 66560
#define XA_STAGE 16384
#define XA_SMEM (XA_XOFF + 2 * XA_STAGE)

__global__ __launch_bounds__(256)
void xa_mma(const float* __restrict__ L2, const __half* __restrict__ Xh,
            const __half* __restrict__ Xl, float* __restrict__ xa)
{
    extern __shared__ char smem[];
    const uint32_t sbase = smem_u32(smem);
    const int b  = blockIdx.y;
    const int c0 = blockIdx.x * 64;
    const int t  = threadIdx.x;
    const int L  = t & 31;
    const int w  = t >> 5;

    __half* psh = (__half*)smem;
    __half* psl = (__half*)(smem + XA_PS);
    for (int mr = w; mr < 16; mr += 8) {
        const float* row = L2 + ((size_t)b * 16 + mr) * Nn;
        float mx = -INFINITY;
#pragma unroll
        for (int i = 0; i < 32; i++) mx = fmaxf(mx, __ldg(row + L + 32 * i));
#pragma unroll
        for (int off = 16; off > 0; off >>= 1)
            mx = fmaxf(mx, __shfl_xor_sync(0xffffffffu, mx, off));
        float sum = 0.f;
#pragma unroll
        for (int i = 0; i < 32; i++) sum += __expf(__ldg(row + L + 32 * i) - mx);
#pragma unroll
        for (int off = 16; off > 0; off >>= 1)
            sum += __shfl_xor_sync(0xffffffffu, sum, off);
        const float inv = 1.0f / sum;
#pragma unroll
        for (int i = 0; i < 32; i++) {
            float e = __expf(__ldg(row + L + 32 * i) - mx) * inv;
            __half h = __float2half(e);
            psh[mr * PS_STRIDE + L + 32 * i] = h;
            psl[mr * PS_STRIDE + L + 32 * i] = __float2half(e - __half2float(h));
        }
    }
    __syncthreads();

#define XA_LOAD(I)                                                                        \
    do {                                                                                  \
        const int s_ = (I) & 1; const int k0_ = (I) * 64;                                 \
        const uint32_t xb_ = sbase + XA_XOFF + s_ * XA_STAGE;                             \
        const int row = t >> 2; const int cb = (t & 3) * 2;                               \
        const __half* gh = Xh + ((size_t)(b * Nn + k0_ + row)) * Cn + c0 + cb * 8;        \
        const __half* gl = Xl + ((size_t)(b * Nn + k0_ + row)) * Cn + c0 + cb * 8;        \
        _Pragma("unroll")                                                                 \
        for (int j = 0; j < 2; j++) {                                                     \
            uint32_t o = (uint32_t)(row * 128 + (cb + j) * 16) ^ ((uint32_t)(row & 7) << 4); \
            cp_async16(xb_ + o, gh + j * 8);                                              \
            cp_async16(xb_ + 8192 + o, gl + j * 8);                                       \
        }                                                                                 \
        asm volatile("cp.async.commit_group;" ::: "memory");                              \
    } while (0)

    float acc[4] = {0.f, 0.f, 0.f, 0.f};
    XA_LOAD(0);
    XA_LOAD(1);

    const int arow = L & 15;
    const int asel = ((L >> 4) & 1) * 16;
    const int brl  = L & 15;
    const uint32_t ph_b = sbase;
    const uint32_t pl_b = sbase + XA_PS;

#pragma unroll 1
    for (int kt = 0; kt < 16; kt++) {
        if (kt < 15) asm volatile("cp.async.wait_group 1;" ::: "memory");
        else         asm volatile("cp.async.wait_group 0;" ::: "memory");
        __syncthreads();
        const uint32_t xb_ = sbase + XA_XOFF + (kt & 1) * XA_STAGE;
#pragma unroll
        for (int ks = 0; ks < 4; ks++) {
            const int kbyte = (kt * 64 + ks * 16) * 2 + asel;
            uint32_t pa[4], pb2[4];
            ldx4(pa,  ph_b + (uint32_t)(arow * (PS_STRIDE * 2) + kbyte));
            ldx4(pb2, pl_b + (uint32_t)(arow * (PS_STRIDE * 2) + kbyte));
            const int r = ks * 16 + brl;
            uint32_t ob_ = (uint32_t)(r * 128 + w * 16) ^ ((uint32_t)(r & 7) << 4);
            uint32_t bh[2], bl2[2];
            ldx2t(bh,  xb_ + ob_);
            ldx2t(bl2, xb_ + 8192 + ob_);
            mma16816(acc, pa,  bh[0],  bh[1]);
            mma16816(acc, pa,  bl2[0], bl2[1]);
            mma16816(acc, pb2, bh[0],  bh[1]);
        }
        if (kt + 2 < 16) { __syncthreads(); XA_LOAD(kt + 2); }
    }
#undef XA_LOAD

    const int g  = L >> 2;
    const int cq = (L & 3) * 2;
    const int c  = c0 + w * 8 + cq;
    *(float2*)(xa + ((size_t)b * 16 + g)     * Cn + c) = make_float2(acc[0], acc[1]);
    *(float2*)(xa + ((size_t)b * 16 + g + 8) * Cn + c) = make_float2(acc[2], acc[3]);
}

// ================= final (unchanged from R11/R12) =================
__global__ __launch_bounds__(512)
void final_kernel(const float* __restrict__ L1, const float* __restrict__ AFo,
                  const float* __restrict__ bo, float* __restrict__ out)
{
    __shared__ float4 afo4[Mn * 128];
    __shared__ float  l1s[64 * 16];
    __shared__ float4 bo4[128];
    const int b    = blockIdx.y;
    const int n0   = blockIdx.x * 64;
    const int tid  = threadIdx.x;
    const int warp = tid >> 5;
    const int lane = tid & 31;

    {
        const float4* s = (const float4*)(AFo + (size_t)b * Mn * Cn);
        for (int i = tid; i < 2048; i += 512) afo4[i] = s[i];
        const float4* sl = (const float4*)(L1 + ((size_t)b * Nn + n0) * 16);
        if (tid < 256) ((float4*)l1s)[tid] = sl[tid];
        if (tid < 128) bo4[tid] = ((const float4*)bo)[tid];
    }
    __syncthreads();

#pragma unroll 1
    for (int t = 0; t < 4; t++) {
        const int tok = warp * 4 + t;
        float lg[16];
#pragma unroll
        for (int m = 0; m < Mn; m++) lg[m] = l1s[tok * 16 + m];
        float mx = lg[0];
#pragma unroll
        for (int m = 1; m < Mn; m++) mx = fmaxf(mx, lg[m]);
        float s = 0.f;
#pragma unroll
        for (int m = 0; m < Mn; m++) { lg[m] = __expf(lg[m] - mx); s += lg[m]; }
        const float inv = 1.0f / s;

        float4* orow = (float4*)(out + ((size_t)b * Nn + n0 + tok) * Cn);
#pragma unroll 1
        for (int kc = 0; kc < 4; kc++) {
            const int cidx = kc * 32 + lane;
            float4 acc = make_float4(0.f, 0.f, 0.f, 0.f);
#pragma unroll
            for (int m = 0; m < Mn; m++) {
                float4 f = afo4[m * 128 + cidx];
                acc.x = fmaf(lg[m], f.x, acc.x);
                acc.y = fmaf(lg[m], f.y, acc.y);
                acc.z = fmaf(lg[m], f.z, acc.z);
                acc.w = fmaf(lg[m], f.w, acc.w);
            }
            float4 bb = bo4[cidx];
            acc.x = acc.x * inv + bb.x;
            acc.y = acc.y * inv + bb.y;
            acc.z = acc.z * inv + bb.z;
            acc.w = acc.w * inv + bb.w;
            orow[cidx] = acc;
        }
    }
}

// ================= launch =================
extern "C" void kernel_launch(void* const* d_in, const int* in_sizes, int n_in,
                              void* d_out, int out_size)
{
    const float* x  = (const float*)d_in[0];
    const float* Wq = (const float*)d_in[1];
    const float* bq = (const float*)d_in[2];
    const float* Wk = (const float*)d_in[3];
    const float* Wv = (const float*)d_in[5];
    const float* bv = (const float*)d_in[6];
    const float* Wo = (const float*)d_in[7];
    const float* bo = (const float*)d_in[8];
    float* out = (float*)d_out;

    float *xp, *A, *bqA, *bvo, *WqT, *WvT, *WoT, *WcT, *L1, *L2, *xa, *AFo;
    __half *xh, *xl, *aqkh, *aqkl;
    cudaGetSymbolAddress((void**)&xp,   g_xp);
    cudaGetSymbolAddress((void**)&A,    g_A);
    cudaGetSymbolAddress((void**)&bqA,  g_bqA);
    cudaGetSymbolAddress((void**)&bvo,  g_bvo);
    cudaGetSymbolAddress((void**)&WqT,  g_WqT);
    cudaGetSymbolAddress((void**)&WvT,  g_WvT);
    cudaGetSymbolAddress((void**)&WoT,  g_WoT);
    cudaGetSymbolAddress((void**)&WcT,  g_WcT);
    cudaGetSymbolAddress((void**)&L1,   g_L1);
    cudaGetSymbolAddress((void**)&L2,   g_L2);
    cudaGetSymbolAddress((void**)&xa,   g_xa);
    cudaGetSymbolAddress((void**)&AFo,  g_AFo);
    cudaGetSymbolAddress((void**)&xh,   g_xh);
    cudaGetSymbolAddress((void**)&xl,   g_xl);
    cudaGetSymbolAddress((void**)&aqkh, g_aqkh);
    cudaGetSymbolAddress((void**)&aqkl, g_aqkl);

    static int attr_set = 0;
    if (!attr_set) {
        cudaFuncSetAttribute(gemm_nn,      cudaFuncAttributeMaxDynamicSharedMemorySize, GEMM_SMEM);
        cudaFuncSetAttribute(gemm_awc,     cudaFuncAttributeMaxDynamicSharedMemorySize, GEMM_SMEM);
        cudaFuncSetAttribute(gemm_aqk_h,   cudaFuncAttributeMaxDynamicSharedMemorySize, GEMM_SMEM);
        cudaFuncSetAttribute(logits12_mma, cudaFuncAttributeMaxDynamicSharedMemorySize, LG_SMEM);
        cudaFuncSetAttribute(xa_mma,       cudaFuncAttributeMaxDynamicSharedMemorySize, XA_SMEM);
        attr_set = 1;
    }

    // 1. prep: transposes + bvo
    prep_kernel<<<dim3(16, 16, 4), dim3(32, 8)>>>(Wq, Wv, Wo, bv, WqT, WvT, WoT, bvo);
    // 2. split x -> fp16 h/l + pooled xp
    split_pool_kernel<<<1024, 512>>>(x, xh, xl, xp);
    // 3. A = xp@WqT + bq  AND  WcT = WvT@WoT (merged, 192 blocks = one wave+)
    gemm_awc<<<192, 256, GEMM_SMEM>>>(xp, WqT, bq, A, WvT, WoT, WcT);
    // 4. Aq|Ak -> fp16 h/l packed (fused cvt)
    gemm_aqk_h<<<dim3(16, 16), 256, GEMM_SMEM>>>(A, Wq, Wk, aqkh, aqkl);
    // 5. bqA = A . bq
    rowdot_kernel<<<128, 256>>>(A, bq, bqA);
    // 6-7. logits + xa (fp16 mma)
    logits12_mma<<<dim3(8, 64), 256, LG_SMEM>>>(xh, xl, aqkh, aqkl, bqA, L1, L2);
    xa_mma<<<dim3(8, 64), 256, XA_SMEM>>>(L2, xh, xl, xa);
    // 8. AFo = xa@WcT + bvo
    gemm_nn<<<dim3(8, 16), 256, GEMM_SMEM>>>(xa, WcT, WcT, bvo, AFo, AFo, 8);
    // 9. final combine
    final_kernel<<<dim3(16, 64), 512>>>(L1, AFo, bo, out);
}